// round 9
// baseline (speedup 1.0000x reference)
#include <cuda_runtime.h>
#include <cuda_bf16.h>
#include <math.h>
#include <float.h>
#include <stdint.h>

// ================= geometry =================
#define NTHR 256
#define MTOK 128

// smem byte map (fp8 images)
#define XA_BASE   0          // X / raw-F fp8 image: 128 rows x 256B (32 KB)
#define H_BASE    32768      // H fp8 image: 128 rows x 512B (64 KB); later dists+stats
#define WB_BASE   98304      // 2 x 16 KB weight chunk buffers
#define GG2_BASE  131072     // 256 f32: gamma^2
#define GB_BASE   132096     // 256 f32: gamma*beta
#define MBAR_BASE 133120     // 2 x 8B mbarriers
#define SMEM_BYTES 133152

// inside H region, used AFTER GEMM2 is done
#define PART_OFF  (H_BASE + 40960)   // [128][2][5] f32 partial sums
#define MU_OFF    (H_BASE + 46080)
#define R_OFF     (H_BASE + 46592)
#define FSQ_OFF   (H_BASE + 47104)
#define GM_OFF    (H_BASE + 47616)
#define CM_OFF    (H_BASE + 47872)

#define DIST_STRIDE 272

// device scratch: pre-swizzled fp8 weight images, 16KB chunks
__device__ uint4 g_W1t[8192];    // 8 chunks (nb*2+kc): n128 x k128, 128B rows
__device__ uint4 g_W2t[8192];    // 8 chunks (nc*4+kc): n128 x k128, 128B rows, k-sub perm
__device__ uint4 g_Memt[1024];   // 1 chunk: 64 rows x k256, 256B rows, gamma-scaled, k-sub perm
__device__ float g_gm[64];
__device__ float g_cM[64];
__device__ float g_cons[3];      // Sbb, Sgb, Sgg

// ================= asm helpers =================
__device__ __forceinline__ uint32_t smem_u32(const void* p) {
    uint32_t a;
    asm("{ .reg .u64 t; cvta.to.shared.u64 t, %1; cvt.u32.u64 %0, t; }" : "=r"(a) : "l"(p));
    return a;
}
#define LDSM4(r0, r1, r2, r3, a) \
    asm volatile("ldmatrix.sync.aligned.m8n8.x4.shared.b16 {%0,%1,%2,%3}, [%4];" \
        : "=r"(r0), "=r"(r1), "=r"(r2), "=r"(r3) : "r"(a))
#define STSM4(a, r0, r1, r2, r3) \
    asm volatile("stmatrix.sync.aligned.m8n8.x4.shared.b16 [%0], {%1,%2,%3,%4};" \
        :: "r"(a), "r"(r0), "r"(r1), "r"(r2), "r"(r3) : "memory")

#define MBARRIER_INIT(addr, cnt) \
    asm volatile("mbarrier.init.shared.b64 [%0], %1;" :: "r"((uint32_t)(addr)), "r"((uint32_t)(cnt)) : "memory")
#define MBAR_EXPECT(addr, bytes) \
    asm volatile("mbarrier.arrive.expect_tx.shared.b64 _, [%0], %1;" \
        :: "r"((uint32_t)(addr)), "r"((uint32_t)(bytes)) : "memory")
#define BULK_G2S(dst, src, bytes, mbar) \
    asm volatile("cp.async.bulk.shared::cta.global.mbarrier::complete_tx::bytes [%0], [%1], %2, [%3];" \
        :: "r"((uint32_t)(dst)), "l"(src), "r"((uint32_t)(bytes)), "r"((uint32_t)(mbar)) : "memory")

#define MBAR_WAIT(addr, par) do { \
    uint32_t _m = (uint32_t)(addr), _p = (uint32_t)(par), _d; \
    asm volatile("{\n\t.reg .pred p;\n\t" \
        "mbarrier.try_wait.parity.acquire.cta.shared::cta.b64 p, [%1], %2;\n\t" \
        "selp.b32 %0, 1, 0, p;\n\t}" : "=r"(_d) : "r"(_m), "r"(_p) : "memory"); \
    if (!_d) { \
        asm volatile("{\n\t.reg .pred P1;\n\t" \
            "WL_%=:\n\t" \
            "mbarrier.try_wait.parity.acquire.cta.shared::cta.b64 P1, [%0], %1, 0x989680;\n\t" \
            "@P1 bra.uni WD_%=;\n\t" \
            "bra.uni WL_%=;\n\t" \
            "WD_%=:\n\t}" :: "r"(_m), "r"(_p) : "memory"); \
    } \
} while (0)

// fp8 mma: m16n8k32 e4m3 x e4m3 -> f32
__device__ __forceinline__ void mma8(float* d, const uint32_t* a, const uint32_t* b) {
    asm volatile(
        "mma.sync.aligned.m16n8k32.row.col.f32.e4m3.e4m3.f32 "
        "{%0,%1,%2,%3}, {%4,%5,%6,%7}, {%8,%9}, {%0,%1,%2,%3};"
        : "+f"(d[0]), "+f"(d[1]), "+f"(d[2]), "+f"(d[3])
        : "r"(a[0]), "r"(a[1]), "r"(a[2]), "r"(a[3]), "r"(b[0]), "r"(b[1]));
}
// pack 2 floats -> 2 e4m3 (low byte = a)
__device__ __forceinline__ uint32_t pk8(float a, float b) {
    uint16_t r;
    asm("cvt.rn.satfinite.e4m3x2.f32 %0, %1, %2;" : "=h"(r) : "f"(b), "f"(a));
    return (uint32_t)r;
}
// lane exchange: build 4-byte groups for stmatrix (A=j0 pair u16, B=j1 pair u16)
__device__ __forceinline__ uint32_t exch(uint32_t A, uint32_t B, int odd) {
    uint32_t send = odd ? A : B;
    uint32_t recv = __shfl_xor_sync(0xffffffffu, send, 1);
    return odd ? (recv | (B << 16)) : (A | (recv << 16));
}
// k-sub permutation: swap sub 4-7 <-> 8-11 within each 16-group
__device__ __forceinline__ int ksubperm(int kl) {
    int sub = kl & 15;
    if (((sub >> 2) ^ (sub >> 3)) & 1) sub ^= 12;
    return (kl & ~15) | sub;
}

// ================= prep kernels =================
__global__ void prep_weights2(const float* __restrict__ W1, const float* __restrict__ W2,
                              const float* __restrict__ Mem, const float* __restrict__ lng) {
    int e = blockIdx.x * 256 + threadIdx.x;
    if (e < 131072) {                               // W1: [k=256][n=512] (no perm)
        int n = e >> 8, k = e & 255;
        int q = (n >> 7) * 2 + (k >> 7);
        int np = n & 127, kl = k & 127;
        int c = kl >> 4;
        uint32_t off = (uint32_t)q * 16384u + np * 128u
                     + (uint32_t)(((c ^ (np & 7)) << 4) | (kl & 15));
        uint32_t p = pk8(W1[k * 512 + n], 0.f);
        *((uint8_t*)g_W1t + off) = (uint8_t)(p & 0xFF);
    } else if (e < 262144) {                        // W2: [k=512][n=256], k-sub perm
        int x = e - 131072;
        int n = x >> 9, k = x & 511;
        int q = (n >> 7) * 4 + (k >> 7);
        int np = n & 127, kl = ksubperm(k & 127);
        int c = kl >> 4;
        uint32_t off = (uint32_t)q * 16384u + np * 128u
                     + (uint32_t)(((c ^ (np & 7)) << 4) | (kl & 15));
        uint32_t p = pk8(W2[k * 256 + n], 0.f);
        *((uint8_t*)g_W2t + off) = (uint8_t)(p & 0xFF);
    } else if (e < 278528) {                        // Memt: 64 rows x k256, gamma-scaled, perm
        int x = e - 262144;
        int m = x >> 8, k = x & 255;
        float v = (m < 50) ? Mem[m * 256 + k] * lng[k] : 0.f;
        int kl = ksubperm(k);
        int c = kl >> 4;
        int cp = (c & 8) | ((c & 7) ^ (m & 7));
        uint32_t off = (uint32_t)m * 256u + (uint32_t)((cp << 4) | (kl & 15));
        uint32_t p = pk8(v, 0.f);
        *((uint8_t*)g_Memt + off) = (uint8_t)(p & 0xFF);
    }
}

__global__ void prep_red(const float* __restrict__ Mem, const float* __restrict__ lng,
                         const float* __restrict__ lnb) {   // <<<65, 32>>>
    int b = blockIdx.x, lane = threadIdx.x;
    if (b < 64) {
        float msq = 0.f, gm = 0.f, bm = 0.f;
        if (b < 50) {
            #pragma unroll
            for (int j = 0; j < 8; j++) {
                int c = lane + 32 * j;
                float mv = Mem[b * 256 + c];
                msq += mv * mv; gm += lng[c] * mv; bm += lnb[c] * mv;
            }
        }
        #pragma unroll
        for (int o = 16; o; o >>= 1) {
            msq += __shfl_xor_sync(0xffffffffu, msq, o);
            gm  += __shfl_xor_sync(0xffffffffu, gm,  o);
            bm  += __shfl_xor_sync(0xffffffffu, bm,  o);
        }
        if (lane == 0) { g_gm[b] = gm; g_cM[b] = msq - 2.f * bm; }
    } else {
        float sbb = 0.f, sgb = 0.f, sgg = 0.f;
        #pragma unroll
        for (int j = 0; j < 8; j++) {
            int c = lane + 32 * j;
            float gv = lng[c], bv = lnb[c];
            sgg += gv * gv; sgb += gv * bv; sbb += bv * bv;
        }
        #pragma unroll
        for (int o = 16; o; o >>= 1) {
            sbb += __shfl_xor_sync(0xffffffffu, sbb, o);
            sgb += __shfl_xor_sync(0xffffffffu, sgb, o);
            sgg += __shfl_xor_sync(0xffffffffu, sgg, o);
        }
        if (lane == 0) { g_cons[0] = sbb; g_cons[1] = sgb; g_cons[2] = sgg; }
    }
}

// chunk source: 0..7 W1, 8..15 W2, 16 Mem
__device__ __forceinline__ const uint4* chunk_src(int q) {
    return (q < 8) ? (g_W1t + q * 1024)
         : (q < 16) ? (g_W2t + (q - 8) * 1024)
                    : g_Memt;
}

// ================= main fused kernel =================
__global__ __launch_bounds__(NTHR, 1)
void ipm_mma(const float* __restrict__ X,
             const float* __restrict__ b1, const float* __restrict__ b2,
             const float* __restrict__ lng, const float* __restrict__ lnb,
             float* __restrict__ out, int ntok)
{
    extern __shared__ __align__(1024) char smem[];
    const uint32_t sb = smem_u32(smem);
    const int tid  = threadIdx.x;
    const int lane = tid & 31;
    const int w    = tid >> 5;
    const int mw   = w & 3;
    const int nw   = w >> 2;
    const int tok0 = blockIdx.x * MTOK;
    const int oddl = lane & 1;

    float* sGg2 = reinterpret_cast<float*>(smem + GG2_BASE);
    float* sGb  = reinterpret_cast<float*>(smem + GB_BASE);
    float* sMu  = reinterpret_cast<float*>(smem + MU_OFF);
    float* sR   = reinterpret_cast<float*>(smem + R_OFF);
    float* sFsq = reinterpret_cast<float*>(smem + FSQ_OFF);
    float* sGm  = reinterpret_cast<float*>(smem + GM_OFF);
    float* sCM  = reinterpret_cast<float*>(smem + CM_OFF);

    const uint32_t lrow16 = lane & 15;
    const uint32_t asel   = lane >> 4;
    const uint32_t sxr    = lane & 7;
    const uint32_t bsel   = (lane >> 3) & 1;
    const uint32_t brow8  = (lane & 7) + ((lane >> 4) << 3);

    const uint32_t mb0 = sb + MBAR_BASE;
    const uint32_t mb1 = sb + MBAR_BASE + 8;

    // -------- prologue --------
    if (tid == 0) {
        MBARRIER_INIT(mb0, 1);
        MBARRIER_INIT(mb1, 1);
    }
    __syncthreads();
    if (tid == 0) {
        MBAR_EXPECT(mb0, 16384);
        BULK_G2S(sb + WB_BASE,         (const void*)chunk_src(0), 16384, mb0);
        MBAR_EXPECT(mb1, 16384);
        BULK_G2S(sb + WB_BASE + 16384, (const void*)chunk_src(1), 16384, mb1);
    }
    {
        float gv = lng[tid], bv = lnb[tid];
        sGg2[tid] = gv * gv;
        sGb[tid]  = gv * bv;
    }
    // X -> fp8 swizzled (128 rows x 256B)
    for (int q = tid; q < MTOK * 64; q += NTHR) {
        int r = q >> 6, k = (q & 63) * 4;
        int rg = tok0 + r; if (rg >= ntok) rg = ntok - 1;
        float4 v = *reinterpret_cast<const float4*>(&X[(long)rg * 256 + k]);
        uint32_t lo = pk8(v.x, v.y), hi = pk8(v.z, v.w);
        uint32_t pkd = lo | (hi << 16);
        int c = k >> 4;
        int cp = (c & 8) | ((c & 7) ^ (r & 7));
        *reinterpret_cast<uint32_t*>(smem + XA_BASE + r * 256 + (cp << 4) + (k & 15)) = pkd;
    }
    __syncthreads();

    // A-row bases
    uint32_t aX[2], aH[2];
    #pragma unroll
    for (int t = 0; t < 2; t++) {
        aX[t] = sb + XA_BASE + (mw * 32 + 16 * t + lrow16) * 256;
        aH[t] = sb + H_BASE  + (mw * 32 + 16 * t + lrow16) * 512;
    }
    // B-row bases: warp's n64 in weight chunks (128B rows)
    uint32_t bW[2][4];
    #pragma unroll
    for (int b = 0; b < 2; b++)
        #pragma unroll
        for (int g = 0; g < 4; g++)
            bW[b][g] = sb + WB_BASE + b * 16384 + (nw * 64 + 16 * g + brow8) * 128;
    // GEMM3 B-row bases (Mem in buffer 0, 256B rows)
    uint32_t bM[2];
    #pragma unroll
    for (int g = 0; g < 2; g++)
        bM[g] = sb + WB_BASE + (nw * 32 + 16 * g + brow8) * 256;

    // ================= GEMM1: H = relu(X @ W1 + b1) =================
    {
        float acc[2][8][4];
        for (int nb = 0; nb < 4; nb++) {
            #pragma unroll
            for (int t = 0; t < 2; t++)
                #pragma unroll
                for (int j = 0; j < 8; j++)
                    acc[t][j][0] = acc[t][j][1] = acc[t][j][2] = acc[t][j][3] = 0.f;

            for (int kc = 0; kc < 2; kc++) {
                const int q = nb * 2 + kc;
                const int buf = q & 1;
                MBAR_WAIT(buf ? mb1 : mb0, (q >> 1) & 1);
                #pragma unroll
                for (int kk = 0; kk < 4; kk++) {
                    uint32_t a[2][4], bfr[8][2];
                    uint32_t cA = (uint32_t)(2 * (kc * 4 + kk)) + asel;
                    uint32_t ksw = (((cA & 8) | ((cA & 7) ^ sxr)) << 4);
                    uint32_t ksb = (((uint32_t)(2 * kk) + bsel) ^ sxr) << 4;
                    #pragma unroll
                    for (int t = 0; t < 2; t++) LDSM4(a[t][0], a[t][1], a[t][2], a[t][3], aX[t] + ksw);
                    #pragma unroll
                    for (int g = 0; g < 4; g++) {
                        uint32_t r0, r1, r2, r3;
                        LDSM4(r0, r1, r2, r3, bW[buf][g] + ksb);
                        bfr[2 * g][0] = r0; bfr[2 * g][1] = r1;
                        bfr[2 * g + 1][0] = r2; bfr[2 * g + 1][1] = r3;
                    }
                    #pragma unroll
                    for (int t = 0; t < 2; t++)
                        #pragma unroll
                        for (int j = 0; j < 8; j++) mma8(acc[t][j], a[t], bfr[j]);
                }

                if (kc == 1) {   // epilogue: +b1, relu, fp8 pack+exchange -> H
                    const int n0 = nb * 128 + nw * 64;
                    #pragma unroll
                    for (int t = 0; t < 2; t++) {
                        #pragma unroll
                        for (int gg = 0; gg < 2; gg++) {
                            uint32_t rr[2][2];
                            #pragma unroll
                            for (int gi = 0; gi < 2; gi++) {
                                int g = 2 * gg + gi, j0 = 2 * g, j1 = 2 * g + 1;
                                float2 bc0 = __ldg((const float2*)&b1[n0 + 16 * g + 2 * (lane & 3)]);
                                float2 bc1 = __ldg((const float2*)&b1[n0 + 16 * g + 8 + 2 * (lane & 3)]);
                                #pragma unroll
                                for (int rh = 0; rh < 2; rh++) {
                                    uint32_t A = pk8(fmaxf(acc[t][j0][2 * rh] + bc0.x, 0.f),
                                                     fmaxf(acc[t][j0][2 * rh + 1] + bc0.y, 0.f));
                                    uint32_t B = pk8(fmaxf(acc[t][j1][2 * rh] + bc1.x, 0.f),
                                                     fmaxf(acc[t][j1][2 * rh + 1] + bc1.y, 0.f));
                                    rr[gi][rh] = exch(A, B, oddl);
                                }
                            }
                            uint32_t jc = (uint32_t)(nb * 8 + nw * 4 + 2 * gg) + asel;
                            uint32_t cp = (jc & 24) | ((jc & 7) ^ sxr);
                            STSM4(aH[t] + (cp << 4), rr[0][0], rr[0][1], rr[1][0], rr[1][1]);
                        }
                    }
                }
                __syncthreads();
                if (q + 2 < 17 && tid == 0) {
                    uint32_t m = buf ? mb1 : mb0;
                    MBAR_EXPECT(m, 16384);
                    BULK_G2S(sb + WB_BASE + buf * 16384, (const void*)chunk_src(q + 2), 16384, m);
                }
            }
        }
    }

    // ================= GEMM2: rawF = H @ W2 + b2 (5-sum stats on the fly) =================
    float st[2][2][5];
    #pragma unroll
    for (int t = 0; t < 2; t++)
        #pragma unroll
        for (int h = 0; h < 2; h++)
            #pragma unroll
            for (int i = 0; i < 5; i++) st[t][h][i] = 0.f;

    {
        float acc[2][8][4];
        for (int nc = 0; nc < 2; nc++) {
            #pragma unroll
            for (int t = 0; t < 2; t++)
                #pragma unroll
                for (int j = 0; j < 8; j++)
                    acc[t][j][0] = acc[t][j][1] = acc[t][j][2] = acc[t][j][3] = 0.f;

            for (int kc = 0; kc < 4; kc++) {
                const int q = 8 + nc * 4 + kc;
                const int buf = q & 1;
                MBAR_WAIT(buf ? mb1 : mb0, (q >> 1) & 1);
                #pragma unroll
                for (int kk = 0; kk < 4; kk++) {
                    uint32_t a[2][4], bfr[8][2];
                    uint32_t cA = (uint32_t)(2 * (kc * 4 + kk)) + asel;
                    uint32_t ksw = (((cA & 24) | ((cA & 7) ^ sxr)) << 4);
                    uint32_t ksb = (((uint32_t)(2 * kk) + bsel) ^ sxr) << 4;
                    #pragma unroll
                    for (int t = 0; t < 2; t++) LDSM4(a[t][0], a[t][1], a[t][2], a[t][3], aH[t] + ksw);
                    #pragma unroll
                    for (int g = 0; g < 4; g++) {
                        uint32_t r0, r1, r2, r3;
                        LDSM4(r0, r1, r2, r3, bW[buf][g] + ksb);
                        bfr[2 * g][0] = r0; bfr[2 * g][1] = r1;
                        bfr[2 * g + 1][0] = r2; bfr[2 * g + 1][1] = r3;
                    }
                    #pragma unroll
                    for (int t = 0; t < 2; t++)
                        #pragma unroll
                        for (int j = 0; j < 8; j++) mma8(acc[t][j], a[t], bfr[j]);
                }

                if (kc == 3) {   // epilogue: +b2, stats, fp8 F -> XA
                    const int n0 = nc * 128 + nw * 64;
                    #pragma unroll
                    for (int t = 0; t < 2; t++) {
                        #pragma unroll
                        for (int gg = 0; gg < 2; gg++) {
                            uint32_t rr[2][2];
                            #pragma unroll
                            for (int gi = 0; gi < 2; gi++) {
                                int g = 2 * gg + gi, j0 = 2 * g, j1 = 2 * g + 1;
                                const int c00 = n0 + 16 * g + 2 * (lane & 3);
                                const int c10 = c00 + 8;
                                float2 bc0 = __ldg((const float2*)&b2[c00]);
                                float2 bc1 = __ldg((const float2*)&b2[c10]);
                                float2 G0 = *reinterpret_cast<float2*>(sGg2 + c00);
                                float2 G1 = *reinterpret_cast<float2*>(sGg2 + c10);
                                float2 E0 = *reinterpret_cast<float2*>(sGb + c00);
                                float2 E1 = *reinterpret_cast<float2*>(sGb + c10);
                                float v00 = acc[t][j0][0] + bc0.x, v01 = acc[t][j0][1] + bc0.y;
                                float v02 = acc[t][j0][2] + bc0.x, v03 = acc[t][j0][3] + bc0.y;
                                float v10 = acc[t][j1][0] + bc1.x, v11 = acc[t][j1][1] + bc1.y;
                                float v12 = acc[t][j1][2] + bc1.x, v13 = acc[t][j1][3] + bc1.y;
                                st[t][0][0] += v00 + v01 + v10 + v11;
                                st[t][0][1] += v00 * v00 + v01 * v01 + v10 * v10 + v11 * v11;
                                st[t][0][2] += G0.x * v00 * v00 + G0.y * v01 * v01 + G1.x * v10 * v10 + G1.y * v11 * v11;
                                st[t][0][3] += G0.x * v00 + G0.y * v01 + G1.x * v10 + G1.y * v11;
                                st[t][0][4] += E0.x * v00 + E0.y * v01 + E1.x * v10 + E1.y * v11;
                                st[t][1][0] += v02 + v03 + v12 + v13;
                                st[t][1][1] += v02 * v02 + v03 * v03 + v12 * v12 + v13 * v13;
                                st[t][1][2] += G0.x * v02 * v02 + G0.y * v03 * v03 + G1.x * v12 * v12 + G1.y * v13 * v13;
                                st[t][1][3] += G0.x * v02 + G0.y * v03 + G1.x * v12 + G1.y * v13;
                                st[t][1][4] += E0.x * v02 + E0.y * v03 + E1.x * v12 + E1.y * v13;
                                #pragma unroll
                                for (int rh = 0; rh < 2; rh++) {
                                    uint32_t A = pk8(rh ? v02 : v00, rh ? v03 : v01);
                                    uint32_t B = pk8(rh ? v12 : v10, rh ? v13 : v11);
                                    rr[gi][rh] = exch(A, B, oddl);
                                }
                            }
                            uint32_t jc = (uint32_t)(nc * 8 + nw * 4 + 2 * gg) + asel;
                            uint32_t cp = (jc & 8) | ((jc & 7) ^ sxr);
                            STSM4(aX[t] + (cp << 4), rr[0][0], rr[0][1], rr[1][0], rr[1][1]);
                        }
                    }
                }
                __syncthreads();
                if (q + 2 < 17 && tid == 0) {
                    uint32_t m = buf ? mb1 : mb0;
                    MBAR_EXPECT(m, 16384);
                    BULK_G2S(sb + WB_BASE + buf * 16384, (const void*)chunk_src(q + 2), 16384, m);
                }
            }
        }
    }

    // -------- stats: quad-reduce, partials to smem, combine --------
    {
        #pragma unroll
        for (int t = 0; t < 2; t++)
            #pragma unroll
            for (int h = 0; h < 2; h++)
                #pragma unroll
                for (int i = 0; i < 5; i++) {
                    float s = st[t][h][i];
                    s += __shfl_xor_sync(0xffffffffu, s, 1);
                    s += __shfl_xor_sync(0xffffffffu, s, 2);
                    st[t][h][i] = s;
                }
        if ((lane & 3) == 0) {
            #pragma unroll
            for (int t = 0; t < 2; t++)
                #pragma unroll
                for (int h = 0; h < 2; h++) {
                    int row = mw * 32 + 16 * t + 8 * h + (lane >> 2);
                    float* p = reinterpret_cast<float*>(smem + PART_OFF) + (row * 2 + nw) * 5;
                    #pragma unroll
                    for (int i = 0; i < 5; i++) p[i] = st[t][h][i];
                }
        }
        __syncthreads();

        if (tid < MTOK) {
            const float* p0 = reinterpret_cast<const float*>(smem + PART_OFF) + (tid * 2) * 5;
            float S1 = p0[0] + p0[5], S2 = p0[1] + p0[6], A2 = p0[2] + p0[7];
            float A1g = p0[3] + p0[8], C1 = p0[4] + p0[9];
            float Sbb = __ldg(&g_cons[0]), Sgb = __ldg(&g_cons[1]), Sgg = __ldg(&g_cons[2]);
            float mu = S1 * (1.f / 256.f);
            float var = S2 * (1.f / 256.f) - mu * mu;
            float r = rsqrtf(var + 1e-5f);
            float fsq = r * r * A2 + 2.f * r * C1 - 2.f * mu * r * r * A1g
                      + Sbb - 2.f * mu * r * Sgb + mu * mu * r * r * Sgg;
            sMu[tid] = mu; sR[tid] = r; sFsq[tid] = fsq;
        }
        if (tid < 64) { sGm[tid] = __ldg(&g_gm[tid]); sCM[tid] = __ldg(&g_cM[tid]); }
        __syncthreads();
    }

    // ================= GEMM3: D = rawF @ (gamma.Mem)^T =================
    {
        MBAR_WAIT(mb0, 0);   // Mem chunk (q=16)

        float acc[2][4][4];
        #pragma unroll
        for (int t = 0; t < 2; t++)
            #pragma unroll
            for (int j = 0; j < 4; j++)
                acc[t][j][0] = acc[t][j][1] = acc[t][j][2] = acc[t][j][3] = 0.f;

        #pragma unroll
        for (int kk = 0; kk < 8; kk++) {
            uint32_t a[2][4], bfr[4][2];
            uint32_t cA = (uint32_t)(2 * kk) + asel;
            uint32_t ksw = (((cA & 8) | ((cA & 7) ^ sxr)) << 4);
            uint32_t cB = (uint32_t)(2 * kk) + bsel;
            uint32_t ksb = (((cB & 8) | ((cB & 7) ^ sxr)) << 4);
            #pragma unroll
            for (int t = 0; t < 2; t++) LDSM4(a[t][0], a[t][1], a[t][2], a[t][3], aX[t] + ksw);
            #pragma unroll
            for (int g = 0; g < 2; g++) {
                uint32_t r0, r1, r2, r3;
                LDSM4(r0, r1, r2, r3, bM[g] + ksb);
                bfr[2 * g][0] = r0; bfr[2 * g][1] = r1;
                bfr[2 * g + 1][0] = r2; bfr[2 * g + 1][1] = r3;
            }
            #pragma unroll
            for (int t = 0; t < 2; t++)
                #pragma unroll
                for (int j = 0; j < 4; j++) mma8(acc[t][j], a[t], bfr[j]);
        }

        // distances: d^2 = fsq + cM + 2*r*(mu*gm - D)
        #pragma unroll
        for (int t = 0; t < 2; t++) {
            int rA = mw * 32 + 16 * t + (lane >> 2), rB = rA + 8;
            float fA = sFsq[rA], rrA = sR[rA], muA = sMu[rA];
            float fB = sFsq[rB], rrB = sR[rB], muB = sMu[rB];
            #pragma unroll
            for (int j = 0; j < 4; j++) {
                int g = j >> 1, u = j & 1;
                int c0 = nw * 32 + 16 * g + 8 * u + 2 * (lane & 3);
                float gm0 = sGm[c0], gm1 = sGm[c0 + 1];
                float cm0 = sCM[c0], cm1 = sCM[c0 + 1];
                float2 dA, dB;
                dA.x = sqrtf(fmaxf(fA + cm0 + 2.f * rrA * (muA * gm0 - acc[t][j][0]), 0.f));
                dA.y = sqrtf(fmaxf(fA + cm1 + 2.f * rrA * (muA * gm1 - acc[t][j][1]), 0.f));
                dB.x = sqrtf(fmaxf(fB + cm0 + 2.f * rrB * (muB * gm0 - acc[t][j][2]), 0.f));
                dB.y = sqrtf(fmaxf(fB + cm1 + 2.f * rrB * (muB * gm1 - acc[t][j][3]), 0.f));
                *reinterpret_cast<float2*>(smem + H_BASE + rA * DIST_STRIDE + c0 * 4) = dA;
                *reinterpret_cast<float2*>(smem + H_BASE + rB * DIST_STRIDE + c0 * 4) = dB;
            }
        }
        __syncthreads();
    }

    // ================= top-5 + sigmoid =================
    if (tid < MTOK) {
        const float* dr = reinterpret_cast<const float*>(smem + H_BASE + tid * DIST_STRIDE);
        float b0 = FLT_MAX, bq1 = FLT_MAX, bq2 = FLT_MAX, bq3 = FLT_MAX, bq4 = FLT_MAX;
        #pragma unroll
        for (int m = 0; m < 50; m++) {
            float v = dr[m];
            if (v < bq4) {
                bq4 = v;
                if (bq4 < bq3) { float x = bq3; bq3 = bq4; bq4 = x; }
                if (bq3 < bq2) { float x = bq2; bq2 = bq3; bq3 = x; }
                if (bq2 < bq1) { float x = bq1; bq1 = bq2; bq2 = x; }
                if (bq1 < b0)  { float x = b0;  b0  = bq1; bq1 = x; }
            }
        }
        float avg = (b0 + bq1 + bq2 + bq3 + bq4) * 0.2f;
        int tg = tok0 + tid;
        if (tg < ntok) out[tg] = 1.f / (1.f + expf(1.f - avg));
    }
}

// ================= launch =================
extern "C" void kernel_launch(void* const* d_in, const int* in_sizes, int n_in,
                              void* d_out, int out_size) {
    const float* X   = (const float*)d_in[0];
    const float* Mem = (const float*)d_in[1];
    const float* W1  = (const float*)d_in[2];
    const float* b1  = (const float*)d_in[3];
    const float* W2  = (const float*)d_in[4];
    const float* b2  = (const float*)d_in[5];
    const float* g   = (const float*)d_in[6];
    const float* be  = (const float*)d_in[7];
    float* out = (float*)d_out;

    int ntok = out_size;
    int grid = (ntok + MTOK - 1) / MTOK;

    prep_weights2<<<1088, 256>>>(W1, W2, Mem, g);
    prep_red<<<65, 32>>>(Mem, g, be);

    cudaFuncSetAttribute(ipm_mma, cudaFuncAttributeMaxDynamicSharedMemorySize, SMEM_BYTES);
    ipm_mma<<<grid, NTHR, SMEM_BYTES>>>(X, b1, b2, g, be, out, ntok);
}

// round 10
// speedup vs baseline: 1.2455x; 1.2455x over previous
#include <cuda_runtime.h>
#include <cuda_bf16.h>
#include <math.h>
#include <float.h>
#include <stdint.h>

// ================= geometry =================
#define NTHR 256
#define MTOK 64

// smem byte map (fp8 images, MTOK=64)
#define XA_BASE   0          // X / raw-F fp8 image: 64 rows x 256B (16 KB)
#define H_BASE    16384      // H fp8 image: 64 rows x 512B (32 KB); later dists+stats
#define WB_BASE   49152      // 2 x 16 KB weight chunk buffers
#define GG2_BASE  81920      // 256 f32: gamma^2
#define GB_BASE   82944      // 256 f32: gamma*beta
#define MBAR_BASE 83968      // 2 x 8B mbarriers
#define SMEM_BYTES 84096

// inside H region, used AFTER GEMM2 is done
#define PART_OFF  (H_BASE + 17408)   // [64][4][5] f32 partial sums (5120 B)
#define MU_OFF    (H_BASE + 22528)
#define R_OFF     (H_BASE + 22784)
#define FSQ_OFF   (H_BASE + 23040)
#define GM_OFF    (H_BASE + 23296)
#define CM_OFF    (H_BASE + 23552)

#define DIST_STRIDE 272

// device scratch: pre-swizzled fp8 weight images, 16KB chunks
__device__ uint4 g_W1t[8192];    // 8 chunks (nb*2+kc): n128 x k128, 128B rows
__device__ uint4 g_W2t[8192];    // 8 chunks (nc*4+kc): n128 x k128, 128B rows, k-sub perm
__device__ uint4 g_Memt[1024];   // 1 chunk: 64 rows x k256, 256B rows, gamma-scaled, k-sub perm
__device__ float g_gm[64];
__device__ float g_cM[64];
__device__ float g_cons[3];      // Sbb, Sgb, Sgg

// ================= asm helpers =================
__device__ __forceinline__ uint32_t smem_u32(const void* p) {
    uint32_t a;
    asm("{ .reg .u64 t; cvta.to.shared.u64 t, %1; cvt.u32.u64 %0, t; }" : "=r"(a) : "l"(p));
    return a;
}
#define LDSM4(r0, r1, r2, r3, a) \
    asm volatile("ldmatrix.sync.aligned.m8n8.x4.shared.b16 {%0,%1,%2,%3}, [%4];" \
        : "=r"(r0), "=r"(r1), "=r"(r2), "=r"(r3) : "r"(a))
#define STSM4(a, r0, r1, r2, r3) \
    asm volatile("stmatrix.sync.aligned.m8n8.x4.shared.b16 [%0], {%1,%2,%3,%4};" \
        :: "r"(a), "r"(r0), "r"(r1), "r"(r2), "r"(r3) : "memory")

#define MBARRIER_INIT(addr, cnt) \
    asm volatile("mbarrier.init.shared.b64 [%0], %1;" :: "r"((uint32_t)(addr)), "r"((uint32_t)(cnt)) : "memory")
#define MBAR_EXPECT(addr, bytes) \
    asm volatile("mbarrier.arrive.expect_tx.shared.b64 _, [%0], %1;" \
        :: "r"((uint32_t)(addr)), "r"((uint32_t)(bytes)) : "memory")
#define BULK_G2S(dst, src, bytes, mbar) \
    asm volatile("cp.async.bulk.shared::cta.global.mbarrier::complete_tx::bytes [%0], [%1], %2, [%3];" \
        :: "r"((uint32_t)(dst)), "l"(src), "r"((uint32_t)(bytes)), "r"((uint32_t)(mbar)) : "memory")

#define MBAR_WAIT(addr, par) do { \
    uint32_t _m = (uint32_t)(addr), _p = (uint32_t)(par), _d; \
    asm volatile("{\n\t.reg .pred p;\n\t" \
        "mbarrier.try_wait.parity.acquire.cta.shared::cta.b64 p, [%1], %2;\n\t" \
        "selp.b32 %0, 1, 0, p;\n\t}" : "=r"(_d) : "r"(_m), "r"(_p) : "memory"); \
    if (!_d) { \
        asm volatile("{\n\t.reg .pred P1;\n\t" \
            "WL_%=:\n\t" \
            "mbarrier.try_wait.parity.acquire.cta.shared::cta.b64 P1, [%0], %1, 0x989680;\n\t" \
            "@P1 bra.uni WD_%=;\n\t" \
            "bra.uni WL_%=;\n\t" \
            "WD_%=:\n\t}" :: "r"(_m), "r"(_p) : "memory"); \
    } \
} while (0)

// fp8 mma: m16n8k32 e4m3 x e4m3 -> f32
__device__ __forceinline__ void mma8(float* d, const uint32_t* a, const uint32_t* b) {
    asm volatile(
        "mma.sync.aligned.m16n8k32.row.col.f32.e4m3.e4m3.f32 "
        "{%0,%1,%2,%3}, {%4,%5,%6,%7}, {%8,%9}, {%0,%1,%2,%3};"
        : "+f"(d[0]), "+f"(d[1]), "+f"(d[2]), "+f"(d[3])
        : "r"(a[0]), "r"(a[1]), "r"(a[2]), "r"(a[3]), "r"(b[0]), "r"(b[1]));
}
// pack 2 floats -> 2 e4m3 (low byte = a)
__device__ __forceinline__ uint32_t pk8(float a, float b) {
    uint16_t r;
    asm("cvt.rn.satfinite.e4m3x2.f32 %0, %1, %2;" : "=h"(r) : "f"(b), "f"(a));
    return (uint32_t)r;
}
// lane exchange: build 4-byte groups for stmatrix
__device__ __forceinline__ uint32_t exch(uint32_t A, uint32_t B, int odd) {
    uint32_t send = odd ? A : B;
    uint32_t recv = __shfl_xor_sync(0xffffffffu, send, 1);
    return odd ? (recv | (B << 16)) : (A | (recv << 16));
}
// k-sub permutation: swap sub 4-7 <-> 8-11 within each 16-group
__device__ __forceinline__ int ksubperm(int kl) {
    int sub = kl & 15;
    if (((sub >> 2) ^ (sub >> 3)) & 1) sub ^= 12;
    return (kl & ~15) | sub;
}

// ================= prep kernels =================
__global__ void prep_weights2(const float* __restrict__ W1, const float* __restrict__ W2,
                              const float* __restrict__ Mem, const float* __restrict__ lng) {
    int e = blockIdx.x * 256 + threadIdx.x;
    if (e < 131072) {                               // W1: [k=256][n=512] (no perm)
        int n = e >> 8, k = e & 255;
        int q = (n >> 7) * 2 + (k >> 7);
        int np = n & 127, kl = k & 127;
        int c = kl >> 4;
        uint32_t off = (uint32_t)q * 16384u + np * 128u
                     + (uint32_t)(((c ^ (np & 7)) << 4) | (kl & 15));
        uint32_t p = pk8(W1[k * 512 + n], 0.f);
        *((uint8_t*)g_W1t + off) = (uint8_t)(p & 0xFF);
    } else if (e < 262144) {                        // W2: [k=512][n=256], k-sub perm
        int x = e - 131072;
        int n = x >> 9, k = x & 511;
        int q = (n >> 7) * 4 + (k >> 7);
        int np = n & 127, kl = ksubperm(k & 127);
        int c = kl >> 4;
        uint32_t off = (uint32_t)q * 16384u + np * 128u
                     + (uint32_t)(((c ^ (np & 7)) << 4) | (kl & 15));
        uint32_t p = pk8(W2[k * 256 + n], 0.f);
        *((uint8_t*)g_W2t + off) = (uint8_t)(p & 0xFF);
    } else if (e < 278528) {                        // Memt: 64 rows x k256, gamma-scaled, perm
        int x = e - 262144;
        int m = x >> 8, k = x & 255;
        float v = (m < 50) ? Mem[m * 256 + k] * lng[k] : 0.f;
        int kl = ksubperm(k);
        int c = kl >> 4;
        int cp = (c & 8) | ((c & 7) ^ (m & 7));
        uint32_t off = (uint32_t)m * 256u + (uint32_t)((cp << 4) | (kl & 15));
        uint32_t p = pk8(v, 0.f);
        *((uint8_t*)g_Memt + off) = (uint8_t)(p & 0xFF);
    }
}

__global__ void prep_red(const float* __restrict__ Mem, const float* __restrict__ lng,
                         const float* __restrict__ lnb) {   // <<<65, 32>>>
    int b = blockIdx.x, lane = threadIdx.x;
    if (b < 64) {
        float msq = 0.f, gm = 0.f, bm = 0.f;
        if (b < 50) {
            #pragma unroll
            for (int j = 0; j < 8; j++) {
                int c = lane + 32 * j;
                float mv = Mem[b * 256 + c];
                msq += mv * mv; gm += lng[c] * mv; bm += lnb[c] * mv;
            }
        }
        #pragma unroll
        for (int o = 16; o; o >>= 1) {
            msq += __shfl_xor_sync(0xffffffffu, msq, o);
            gm  += __shfl_xor_sync(0xffffffffu, gm,  o);
            bm  += __shfl_xor_sync(0xffffffffu, bm,  o);
        }
        if (lane == 0) { g_gm[b] = gm; g_cM[b] = msq - 2.f * bm; }
    } else {
        float sbb = 0.f, sgb = 0.f, sgg = 0.f;
        #pragma unroll
        for (int j = 0; j < 8; j++) {
            int c = lane + 32 * j;
            float gv = lng[c], bv = lnb[c];
            sgg += gv * gv; sgb += gv * bv; sbb += bv * bv;
        }
        #pragma unroll
        for (int o = 16; o; o >>= 1) {
            sbb += __shfl_xor_sync(0xffffffffu, sbb, o);
            sgb += __shfl_xor_sync(0xffffffffu, sgb, o);
            sgg += __shfl_xor_sync(0xffffffffu, sgg, o);
        }
        if (lane == 0) { g_cons[0] = sbb; g_cons[1] = sgb; g_cons[2] = sgg; }
    }
}

// chunk source: 0..7 W1, 8..15 W2, 16 Mem
__device__ __forceinline__ const uint4* chunk_src(int q) {
    return (q < 8) ? (g_W1t + q * 1024)
         : (q < 16) ? (g_W2t + (q - 8) * 1024)
                    : g_Memt;
}

// ================= main fused kernel =================
__global__ __launch_bounds__(NTHR, 2)
void ipm_mma(const float* __restrict__ X,
             const float* __restrict__ b1, const float* __restrict__ b2,
             const float* __restrict__ lng, const float* __restrict__ lnb,
             float* __restrict__ out, int ntok)
{
    extern __shared__ __align__(1024) char smem[];
    const uint32_t sb = smem_u32(smem);
    const int tid  = threadIdx.x;
    const int lane = tid & 31;
    const int w    = tid >> 5;
    const int mw   = w & 1;            // 2 M groups of 32 rows
    const int nw   = w >> 1;           // 4 N groups
    const int tok0 = blockIdx.x * MTOK;
    const int oddl = lane & 1;

    float* sGg2 = reinterpret_cast<float*>(smem + GG2_BASE);
    float* sGb  = reinterpret_cast<float*>(smem + GB_BASE);
    float* sMu  = reinterpret_cast<float*>(smem + MU_OFF);
    float* sR   = reinterpret_cast<float*>(smem + R_OFF);
    float* sFsq = reinterpret_cast<float*>(smem + FSQ_OFF);
    float* sGm  = reinterpret_cast<float*>(smem + GM_OFF);
    float* sCM  = reinterpret_cast<float*>(smem + CM_OFF);

    const uint32_t lrow16 = lane & 15;
    const uint32_t asel   = lane >> 4;
    const uint32_t sxr    = lane & 7;
    const uint32_t bsel   = (lane >> 3) & 1;
    const uint32_t brow8  = (lane & 7) + ((lane >> 4) << 3);

    const uint32_t mb0 = sb + MBAR_BASE;
    const uint32_t mb1 = sb + MBAR_BASE + 8;

    // -------- prologue --------
    if (tid == 0) {
        MBARRIER_INIT(mb0, 1);
        MBARRIER_INIT(mb1, 1);
    }
    __syncthreads();
    if (tid == 0) {
        MBAR_EXPECT(mb0, 16384);
        BULK_G2S(sb + WB_BASE,         (const void*)chunk_src(0), 16384, mb0);
        MBAR_EXPECT(mb1, 16384);
        BULK_G2S(sb + WB_BASE + 16384, (const void*)chunk_src(1), 16384, mb1);
    }
    {
        float gv = lng[tid], bv = lnb[tid];
        sGg2[tid] = gv * gv;
        sGb[tid]  = gv * bv;
    }
    // X -> fp8 swizzled (64 rows x 256B)
    for (int q = tid; q < MTOK * 64; q += NTHR) {
        int r = q >> 6, k = (q & 63) * 4;
        int rg = tok0 + r; if (rg >= ntok) rg = ntok - 1;
        float4 v = *reinterpret_cast<const float4*>(&X[(long)rg * 256 + k]);
        uint32_t lo = pk8(v.x, v.y), hi = pk8(v.z, v.w);
        uint32_t pkd = lo | (hi << 16);
        int c = k >> 4;
        int cp = (c & 8) | ((c & 7) ^ (r & 7));
        *reinterpret_cast<uint32_t*>(smem + XA_BASE + r * 256 + (cp << 4) + (k & 15)) = pkd;
    }
    __syncthreads();

    // A-row bases (2 m16 tiles per warp)
    uint32_t aX[2], aH[2];
    #pragma unroll
    for (int t = 0; t < 2; t++) {
        aX[t] = sb + XA_BASE + (mw * 32 + 16 * t + lrow16) * 256;
        aH[t] = sb + H_BASE  + (mw * 32 + 16 * t + lrow16) * 512;
    }
    // B-row bases: warp's n32 in weight chunks (128B rows)
    uint32_t bW[2][2];
    #pragma unroll
    for (int b = 0; b < 2; b++)
        #pragma unroll
        for (int g = 0; g < 2; g++)
            bW[b][g] = sb + WB_BASE + b * 16384 + (nw * 32 + 16 * g + brow8) * 128;
    // GEMM3 B-row base: warp's n16 in Mem chunk (buffer 0, 256B rows)
    const uint32_t bM = sb + WB_BASE + (nw * 16 + brow8) * 256;

    // ================= GEMM1: H = relu(X @ W1 + b1) =================
    {
        float acc[2][4][4];
        for (int nb = 0; nb < 4; nb++) {
            #pragma unroll
            for (int t = 0; t < 2; t++)
                #pragma unroll
                for (int j = 0; j < 4; j++)
                    acc[t][j][0] = acc[t][j][1] = acc[t][j][2] = acc[t][j][3] = 0.f;

            for (int kc = 0; kc < 2; kc++) {
                const int q = nb * 2 + kc;
                const int buf = q & 1;
                MBAR_WAIT(buf ? mb1 : mb0, (q >> 1) & 1);
                #pragma unroll
                for (int kk = 0; kk < 4; kk++) {
                    uint32_t a[2][4], bfr[4][2];
                    uint32_t cA = (uint32_t)(2 * (kc * 4 + kk)) + asel;
                    uint32_t ksw = (((cA & 8) | ((cA & 7) ^ sxr)) << 4);
                    uint32_t ksb = (((uint32_t)(2 * kk) + bsel) ^ sxr) << 4;
                    #pragma unroll
                    for (int t = 0; t < 2; t++) LDSM4(a[t][0], a[t][1], a[t][2], a[t][3], aX[t] + ksw);
                    #pragma unroll
                    for (int g = 0; g < 2; g++) {
                        uint32_t r0, r1, r2, r3;
                        LDSM4(r0, r1, r2, r3, bW[buf][g] + ksb);
                        bfr[2 * g][0] = r0; bfr[2 * g][1] = r1;
                        bfr[2 * g + 1][0] = r2; bfr[2 * g + 1][1] = r3;
                    }
                    #pragma unroll
                    for (int t = 0; t < 2; t++)
                        #pragma unroll
                        for (int j = 0; j < 4; j++) mma8(acc[t][j], a[t], bfr[j]);
                }

                if (kc == 1) {   // epilogue: +b1, relu, fp8 pack+exchange -> H
                    const int n0 = nb * 128 + nw * 32;
                    #pragma unroll
                    for (int t = 0; t < 2; t++) {
                        uint32_t rr[2][2];
                        #pragma unroll
                        for (int gi = 0; gi < 2; gi++) {
                            int j0 = 2 * gi, j1 = 2 * gi + 1;
                            float2 bc0 = __ldg((const float2*)&b1[n0 + 16 * gi + 2 * (lane & 3)]);
                            float2 bc1 = __ldg((const float2*)&b1[n0 + 16 * gi + 8 + 2 * (lane & 3)]);
                            #pragma unroll
                            for (int rh = 0; rh < 2; rh++) {
                                uint32_t A = pk8(fmaxf(acc[t][j0][2 * rh] + bc0.x, 0.f),
                                                 fmaxf(acc[t][j0][2 * rh + 1] + bc0.y, 0.f));
                                uint32_t B = pk8(fmaxf(acc[t][j1][2 * rh] + bc1.x, 0.f),
                                                 fmaxf(acc[t][j1][2 * rh + 1] + bc1.y, 0.f));
                                rr[gi][rh] = exch(A, B, oddl);
                            }
                        }
                        uint32_t jc = (uint32_t)(nb * 8 + nw * 2) + asel;
                        uint32_t cp = (jc & 24) | ((jc & 7) ^ sxr);
                        STSM4(aH[t] + (cp << 4), rr[0][0], rr[0][1], rr[1][0], rr[1][1]);
                    }
                }
                __syncthreads();
                if (q + 2 < 17 && tid == 0) {
                    uint32_t m = buf ? mb1 : mb0;
                    MBAR_EXPECT(m, 16384);
                    BULK_G2S(sb + WB_BASE + buf * 16384, (const void*)chunk_src(q + 2), 16384, m);
                }
            }
        }
    }

    // ================= GEMM2: rawF = H @ W2 + b2 (5-sum stats on the fly) =================
    float st[2][2][5];
    #pragma unroll
    for (int t = 0; t < 2; t++)
        #pragma unroll
        for (int h = 0; h < 2; h++)
            #pragma unroll
            for (int i = 0; i < 5; i++) st[t][h][i] = 0.f;

    {
        float acc[2][4][4];
        for (int nc = 0; nc < 2; nc++) {
            #pragma unroll
            for (int t = 0; t < 2; t++)
                #pragma unroll
                for (int j = 0; j < 4; j++)
                    acc[t][j][0] = acc[t][j][1] = acc[t][j][2] = acc[t][j][3] = 0.f;

            for (int kc = 0; kc < 4; kc++) {
                const int q = 8 + nc * 4 + kc;
                const int buf = q & 1;
                MBAR_WAIT(buf ? mb1 : mb0, (q >> 1) & 1);
                #pragma unroll
                for (int kk = 0; kk < 4; kk++) {
                    uint32_t a[2][4], bfr[4][2];
                    uint32_t cA = (uint32_t)(2 * (kc * 4 + kk)) + asel;
                    uint32_t ksw = (((cA & 24) | ((cA & 7) ^ sxr)) << 4);
                    uint32_t ksb = (((uint32_t)(2 * kk) + bsel) ^ sxr) << 4;
                    #pragma unroll
                    for (int t = 0; t < 2; t++) LDSM4(a[t][0], a[t][1], a[t][2], a[t][3], aH[t] + ksw);
                    #pragma unroll
                    for (int g = 0; g < 2; g++) {
                        uint32_t r0, r1, r2, r3;
                        LDSM4(r0, r1, r2, r3, bW[buf][g] + ksb);
                        bfr[2 * g][0] = r0; bfr[2 * g][1] = r1;
                        bfr[2 * g + 1][0] = r2; bfr[2 * g + 1][1] = r3;
                    }
                    #pragma unroll
                    for (int t = 0; t < 2; t++)
                        #pragma unroll
                        for (int j = 0; j < 4; j++) mma8(acc[t][j], a[t], bfr[j]);
                }

                if (kc == 3) {   // epilogue: +b2, stats, fp8 F -> XA
                    const int n0 = nc * 128 + nw * 32;
                    #pragma unroll
                    for (int t = 0; t < 2; t++) {
                        uint32_t rr[2][2];
                        #pragma unroll
                        for (int gi = 0; gi < 2; gi++) {
                            int j0 = 2 * gi, j1 = 2 * gi + 1;
                            const int c00 = n0 + 16 * gi + 2 * (lane & 3);
                            const int c10 = c00 + 8;
                            float2 bc0 = __ldg((const float2*)&b2[c00]);
                            float2 bc1 = __ldg((const float2*)&b2[c10]);
                            float2 G0 = *reinterpret_cast<float2*>(sGg2 + c00);
                            float2 G1 = *reinterpret_cast<float2*>(sGg2 + c10);
                            float2 E0 = *reinterpret_cast<float2*>(sGb + c00);
                            float2 E1 = *reinterpret_cast<float2*>(sGb + c10);
                            float v00 = acc[t][j0][0] + bc0.x, v01 = acc[t][j0][1] + bc0.y;
                            float v02 = acc[t][j0][2] + bc0.x, v03 = acc[t][j0][3] + bc0.y;
                            float v10 = acc[t][j1][0] + bc1.x, v11 = acc[t][j1][1] + bc1.y;
                            float v12 = acc[t][j1][2] + bc1.x, v13 = acc[t][j1][3] + bc1.y;
                            st[t][0][0] += v00 + v01 + v10 + v11;
                            st[t][0][1] += v00 * v00 + v01 * v01 + v10 * v10 + v11 * v11;
                            st[t][0][2] += G0.x * v00 * v00 + G0.y * v01 * v01 + G1.x * v10 * v10 + G1.y * v11 * v11;
                            st[t][0][3] += G0.x * v00 + G0.y * v01 + G1.x * v10 + G1.y * v11;
                            st[t][0][4] += E0.x * v00 + E0.y * v01 + E1.x * v10 + E1.y * v11;
                            st[t][1][0] += v02 + v03 + v12 + v13;
                            st[t][1][1] += v02 * v02 + v03 * v03 + v12 * v12 + v13 * v13;
                            st[t][1][2] += G0.x * v02 * v02 + G0.y * v03 * v03 + G1.x * v12 * v12 + G1.y * v13 * v13;
                            st[t][1][3] += G0.x * v02 + G0.y * v03 + G1.x * v12 + G1.y * v13;
                            st[t][1][4] += E0.x * v02 + E0.y * v03 + E1.x * v12 + E1.y * v13;
                            #pragma unroll
                            for (int rh = 0; rh < 2; rh++) {
                                uint32_t A = pk8(rh ? v02 : v00, rh ? v03 : v01);
                                uint32_t B = pk8(rh ? v12 : v10, rh ? v13 : v11);
                                rr[gi][rh] = exch(A, B, oddl);
                            }
                        }
                        uint32_t jc = (uint32_t)(nc * 8 + nw * 2) + asel;
                        uint32_t cp = (jc & 8) | ((jc & 7) ^ sxr);
                        STSM4(aX[t] + (cp << 4), rr[0][0], rr[0][1], rr[1][0], rr[1][1]);
                    }
                }
                __syncthreads();
                if (q + 2 < 17 && tid == 0) {
                    uint32_t m = buf ? mb1 : mb0;
                    MBAR_EXPECT(m, 16384);
                    BULK_G2S(sb + WB_BASE + buf * 16384, (const void*)chunk_src(q + 2), 16384, m);
                }
            }
        }
    }

    // -------- stats: quad-reduce, partials to smem, combine --------
    {
        #pragma unroll
        for (int t = 0; t < 2; t++)
            #pragma unroll
            for (int h = 0; h < 2; h++)
                #pragma unroll
                for (int i = 0; i < 5; i++) {
                    float s = st[t][h][i];
                    s += __shfl_xor_sync(0xffffffffu, s, 1);
                    s += __shfl_xor_sync(0xffffffffu, s, 2);
                    st[t][h][i] = s;
                }
        if ((lane & 3) == 0) {
            #pragma unroll
            for (int t = 0; t < 2; t++)
                #pragma unroll
                for (int h = 0; h < 2; h++) {
                    int row = mw * 32 + 16 * t + 8 * h + (lane >> 2);
                    float* p = reinterpret_cast<float*>(smem + PART_OFF) + (row * 4 + nw) * 5;
                    #pragma unroll
                    for (int i = 0; i < 5; i++) p[i] = st[t][h][i];
                }
        }
        __syncthreads();

        if (tid < MTOK) {
            const float* p0 = reinterpret_cast<const float*>(smem + PART_OFF) + (tid * 4) * 5;
            float S1 = p0[0] + p0[5] + p0[10] + p0[15];
            float S2 = p0[1] + p0[6] + p0[11] + p0[16];
            float A2 = p0[2] + p0[7] + p0[12] + p0[17];
            float A1g = p0[3] + p0[8] + p0[13] + p0[18];
            float C1 = p0[4] + p0[9] + p0[14] + p0[19];
            float Sbb = __ldg(&g_cons[0]), Sgb = __ldg(&g_cons[1]), Sgg = __ldg(&g_cons[2]);
            float mu = S1 * (1.f / 256.f);
            float var = S2 * (1.f / 256.f) - mu * mu;
            float r = rsqrtf(var + 1e-5f);
            float fsq = r * r * A2 + 2.f * r * C1 - 2.f * mu * r * r * A1g
                      + Sbb - 2.f * mu * r * Sgb + mu * mu * r * r * Sgg;
            sMu[tid] = mu; sR[tid] = r; sFsq[tid] = fsq;
        }
        if (tid < 64) { sGm[tid] = __ldg(&g_gm[tid]); sCM[tid] = __ldg(&g_cM[tid]); }
        __syncthreads();
    }

    // ================= GEMM3: D = rawF @ (gamma.Mem)^T =================
    {
        MBAR_WAIT(mb0, 0);   // Mem chunk (q=16)

        float acc[2][2][4];
        #pragma unroll
        for (int t = 0; t < 2; t++)
            #pragma unroll
            for (int j = 0; j < 2; j++)
                acc[t][j][0] = acc[t][j][1] = acc[t][j][2] = acc[t][j][3] = 0.f;

        #pragma unroll
        for (int kk = 0; kk < 8; kk++) {
            uint32_t a[2][4], bfr[2][2];
            uint32_t cA = (uint32_t)(2 * kk) + asel;
            uint32_t ksw = (((cA & 8) | ((cA & 7) ^ sxr)) << 4);
            uint32_t cB = (uint32_t)(2 * kk) + bsel;
            uint32_t ksb = (((cB & 8) | ((cB & 7) ^ sxr)) << 4);
            #pragma unroll
            for (int t = 0; t < 2; t++) LDSM4(a[t][0], a[t][1], a[t][2], a[t][3], aX[t] + ksw);
            {
                uint32_t r0, r1, r2, r3;
                LDSM4(r0, r1, r2, r3, bM + ksb);
                bfr[0][0] = r0; bfr[0][1] = r1;
                bfr[1][0] = r2; bfr[1][1] = r3;
            }
            #pragma unroll
            for (int t = 0; t < 2; t++)
                #pragma unroll
                for (int j = 0; j < 2; j++) mma8(acc[t][j], a[t], bfr[j]);
        }

        // distances: d^2 = fsq + cM + 2*r*(mu*gm - D)
        #pragma unroll
        for (int t = 0; t < 2; t++) {
            int rA = mw * 32 + 16 * t + (lane >> 2), rB = rA + 8;
            float fA = sFsq[rA], rrA = sR[rA], muA = sMu[rA];
            float fB = sFsq[rB], rrB = sR[rB], muB = sMu[rB];
            #pragma unroll
            for (int j = 0; j < 2; j++) {
                int c0 = nw * 16 + 8 * j + 2 * (lane & 3);
                float gm0 = sGm[c0], gm1 = sGm[c0 + 1];
                float cm0 = sCM[c0], cm1 = sCM[c0 + 1];
                float2 dA, dB;
                dA.x = sqrtf(fmaxf(fA + cm0 + 2.f * rrA * (muA * gm0 - acc[t][j][0]), 0.f));
                dA.y = sqrtf(fmaxf(fA + cm1 + 2.f * rrA * (muA * gm1 - acc[t][j][1]), 0.f));
                dB.x = sqrtf(fmaxf(fB + cm0 + 2.f * rrB * (muB * gm0 - acc[t][j][2]), 0.f));
                dB.y = sqrtf(fmaxf(fB + cm1 + 2.f * rrB * (muB * gm1 - acc[t][j][3]), 0.f));
                *reinterpret_cast<float2*>(smem + H_BASE + rA * DIST_STRIDE + c0 * 4) = dA;
                *reinterpret_cast<float2*>(smem + H_BASE + rB * DIST_STRIDE + c0 * 4) = dB;
            }
        }
        __syncthreads();
    }

    // ================= top-5 + sigmoid =================
    if (tid < MTOK) {
        const float* dr = reinterpret_cast<const float*>(smem + H_BASE + tid * DIST_STRIDE);
        float b0 = FLT_MAX, bq1 = FLT_MAX, bq2 = FLT_MAX, bq3 = FLT_MAX, bq4 = FLT_MAX;
        #pragma unroll
        for (int m = 0; m < 50; m++) {
            float v = dr[m];
            if (v < bq4) {
                bq4 = v;
                if (bq4 < bq3) { float x = bq3; bq3 = bq4; bq4 = x; }
                if (bq3 < bq2) { float x = bq2; bq2 = bq3; bq3 = x; }
                if (bq2 < bq1) { float x = bq1; bq1 = bq2; bq2 = x; }
                if (bq1 < b0)  { float x = b0;  b0  = bq1; bq1 = x; }
            }
        }
        float avg = (b0 + bq1 + bq2 + bq3 + bq4) * 0.2f;
        int tg = tok0 + tid;
        if (tg < ntok) out[tg] = 1.f / (1.f + expf(1.f - avg));
    }
}

// ================= launch =================
extern "C" void kernel_launch(void* const* d_in, const int* in_sizes, int n_in,
                              void* d_out, int out_size) {
    const float* X   = (const float*)d_in[0];
    const float* Mem = (const float*)d_in[1];
    const float* W1  = (const float*)d_in[2];
    const float* b1  = (const float*)d_in[3];
    const float* W2  = (const float*)d_in[4];
    const float* b2  = (const float*)d_in[5];
    const float* g   = (const float*)d_in[6];
    const float* be  = (const float*)d_in[7];
    float* out = (float*)d_out;

    int ntok = out_size;
    int grid = (ntok + MTOK - 1) / MTOK;

    prep_weights2<<<1088, 256>>>(W1, W2, Mem, g);
    prep_red<<<65, 32>>>(Mem, g, be);

    cudaFuncSetAttribute(ipm_mma, cudaFuncAttributeMaxDynamicSharedMemorySize, SMEM_BYTES);
    ipm_mma<<<grid, NTHR, SMEM_BYTES>>>(X, b1, b2, g, be, out, ntok);
}

// round 11
// speedup vs baseline: 1.2849x; 1.0316x over previous
#include <cuda_runtime.h>
#include <cuda_bf16.h>
#include <math.h>
#include <float.h>
#include <stdint.h>

// ================= geometry =================
#define NTHR 256
#define MTOK 64

// smem byte map (fp8 images, MTOK=64, 8KB weight chunks)
#define XA_BASE   0          // X / raw-F fp8 image: 64 rows x 256B (16 KB)
#define H_BASE    16384      // H fp8 image: 64 rows x 512B (32 KB); later dists+stats
#define WB_BASE   49152      // 2 x 8 KB weight chunk buffers
#define GG2_BASE  65536      // 256 f32: gamma^2
#define GB_BASE   66560      // 256 f32: gamma*beta
#define MBAR_BASE 67584      // 2 x 8B mbarriers
#define SMEM_BYTES 67616

// inside H region, used AFTER GEMM2 is done
#define PART_OFF  (H_BASE + 17408)   // [64][4][5] f32 partial sums (5120 B)
#define MU_OFF    (H_BASE + 22528)
#define R_OFF     (H_BASE + 22784)
#define FSQ_OFF   (H_BASE + 23040)
#define GM_OFF    (H_BASE + 23296)
#define CM_OFF    (H_BASE + 23552)

#define DIST_STRIDE 272

// device scratch: pre-swizzled fp8 weight images, 8KB chunks (n64 x k128, 128B rows)
__device__ uint4 g_W1t[8192];    // 16 chunks: q = (n>>6)*2 + (k>>7)
__device__ uint4 g_W2t[8192];    // 16 chunks: q = (n>>6)*4 + (k>>7)
__device__ uint4 g_Memt[1024];   // 2 chunks: q = k>>7 ; 64 rows, gamma-scaled
__device__ float g_gm[64];
__device__ float g_cM[64];
__device__ float g_cons[3];      // Sbb, Sgb, Sgg

// ================= asm helpers =================
__device__ __forceinline__ uint32_t smem_u32(const void* p) {
    uint32_t a;
    asm("{ .reg .u64 t; cvta.to.shared.u64 t, %1; cvt.u32.u64 %0, t; }" : "=r"(a) : "l"(p));
    return a;
}
#define LDSM4(r0, r1, r2, r3, a) \
    asm volatile("ldmatrix.sync.aligned.m8n8.x4.shared.b16 {%0,%1,%2,%3}, [%4];" \
        : "=r"(r0), "=r"(r1), "=r"(r2), "=r"(r3) : "r"(a))

#define MBARRIER_INIT(addr, cnt) \
    asm volatile("mbarrier.init.shared.b64 [%0], %1;" :: "r"((uint32_t)(addr)), "r"((uint32_t)(cnt)) : "memory")
#define MBAR_EXPECT(addr, bytes) \
    asm volatile("mbarrier.arrive.expect_tx.shared.b64 _, [%0], %1;" \
        :: "r"((uint32_t)(addr)), "r"((uint32_t)(bytes)) : "memory")
#define BULK_G2S(dst, src, bytes, mbar) \
    asm volatile("cp.async.bulk.shared::cta.global.mbarrier::complete_tx::bytes [%0], [%1], %2, [%3];" \
        :: "r"((uint32_t)(dst)), "l"(src), "r"((uint32_t)(bytes)), "r"((uint32_t)(mbar)) : "memory")

#define MBAR_WAIT(addr, par) do { \
    uint32_t _m = (uint32_t)(addr), _p = (uint32_t)(par), _d; \
    asm volatile("{\n\t.reg .pred p;\n\t" \
        "mbarrier.try_wait.parity.acquire.cta.shared::cta.b64 p, [%1], %2;\n\t" \
        "selp.b32 %0, 1, 0, p;\n\t}" : "=r"(_d) : "r"(_m), "r"(_p) : "memory"); \
    if (!_d) { \
        asm volatile("{\n\t.reg .pred P1;\n\t" \
            "WL_%=:\n\t" \
            "mbarrier.try_wait.parity.acquire.cta.shared::cta.b64 P1, [%0], %1, 0x989680;\n\t" \
            "@P1 bra.uni WD_%=;\n\t" \
            "bra.uni WL_%=;\n\t" \
            "WD_%=:\n\t}" :: "r"(_m), "r"(_p) : "memory"); \
    } \
} while (0)

// fp8 mma: m16n8k32 e4m3 x e4m3 -> f32
__device__ __forceinline__ void mma8(float* d, const uint32_t* a, const uint32_t* b) {
    asm volatile(
        "mma.sync.aligned.m16n8k32.row.col.f32.e4m3.e4m3.f32 "
        "{%0,%1,%2,%3}, {%4,%5,%6,%7}, {%8,%9}, {%0,%1,%2,%3};"
        : "+f"(d[0]), "+f"(d[1]), "+f"(d[2]), "+f"(d[3])
        : "r"(a[0]), "r"(a[1]), "r"(a[2]), "r"(a[3]), "r"(b[0]), "r"(b[1]));
}
// pack 2 floats -> 2 e4m3 (low byte = a)
__device__ __forceinline__ uint32_t pk8(float a, float b) {
    uint16_t r;
    asm("cvt.rn.satfinite.e4m3x2.f32 %0, %1, %2;" : "=h"(r) : "f"(b), "f"(a));
    return (uint32_t)r;
}

// ================= prep kernels =================
__global__ void prep_weights2(const float* __restrict__ W1, const float* __restrict__ W2,
                              const float* __restrict__ Mem, const float* __restrict__ lng) {
    int e = blockIdx.x * 256 + threadIdx.x;
    if (e < 131072) {                               // W1: [k=256][n=512]
        int n = e >> 8, k = e & 255;
        int q = (n >> 6) * 2 + (k >> 7);
        int np = n & 63, kl = k & 127;
        int c = kl >> 4;
        uint32_t off = (uint32_t)q * 8192u + np * 128u
                     + (uint32_t)(((c ^ (np & 7)) << 4) | (kl & 15));
        uint32_t p = pk8(W1[k * 512 + n], 0.f);
        *((uint8_t*)g_W1t + off) = (uint8_t)(p & 0xFF);
    } else if (e < 262144) {                        // W2: [k=512][n=256]
        int x = e - 131072;
        int n = x >> 9, k = x & 511;
        int q = (n >> 6) * 4 + (k >> 7);
        int np = n & 63, kl = k & 127;
        int c = kl >> 4;
        uint32_t off = (uint32_t)q * 8192u + np * 128u
                     + (uint32_t)(((c ^ (np & 7)) << 4) | (kl & 15));
        uint32_t p = pk8(W2[k * 256 + n], 0.f);
        *((uint8_t*)g_W2t + off) = (uint8_t)(p & 0xFF);
    } else if (e < 278528) {                        // Memt: 64 rows x k256, gamma-scaled
        int x = e - 262144;
        int m = x >> 8, k = x & 255;
        float v = (m < 50) ? Mem[m * 256 + k] * lng[k] : 0.f;
        int q = k >> 7, kl = k & 127;
        int c = kl >> 4;
        uint32_t off = (uint32_t)q * 8192u + m * 128u
                     + (uint32_t)(((c ^ (m & 7)) << 4) | (kl & 15));
        uint32_t p = pk8(v, 0.f);
        *((uint8_t*)g_Memt + off) = (uint8_t)(p & 0xFF);
    }
}

__global__ void prep_red(const float* __restrict__ Mem, const float* __restrict__ lng,
                         const float* __restrict__ lnb) {   // <<<65, 32>>>
    int b = blockIdx.x, lane = threadIdx.x;
    if (b < 64) {
        float msq = 0.f, gm = 0.f, bm = 0.f;
        if (b < 50) {
            #pragma unroll
            for (int j = 0; j < 8; j++) {
                int c = lane + 32 * j;
                float mv = Mem[b * 256 + c];
                msq += mv * mv; gm += lng[c] * mv; bm += lnb[c] * mv;
            }
        }
        #pragma unroll
        for (int o = 16; o; o >>= 1) {
            msq += __shfl_xor_sync(0xffffffffu, msq, o);
            gm  += __shfl_xor_sync(0xffffffffu, gm,  o);
            bm  += __shfl_xor_sync(0xffffffffu, bm,  o);
        }
        if (lane == 0) { g_gm[b] = gm; g_cM[b] = msq - 2.f * bm; }
    } else {
        float sbb = 0.f, sgb = 0.f, sgg = 0.f;
        #pragma unroll
        for (int j = 0; j < 8; j++) {
            int c = lane + 32 * j;
            float gv = lng[c], bv = lnb[c];
            sgg += gv * gv; sgb += gv * bv; sbb += bv * bv;
        }
        #pragma unroll
        for (int o = 16; o; o >>= 1) {
            sbb += __shfl_xor_sync(0xffffffffu, sbb, o);
            sgb += __shfl_xor_sync(0xffffffffu, sgb, o);
            sgg += __shfl_xor_sync(0xffffffffu, sgg, o);
        }
        if (lane == 0) { g_cons[0] = sbb; g_cons[1] = sgb; g_cons[2] = sgg; }
    }
}

// chunk source: 0..15 W1, 16..31 W2, 32..33 Mem  (512 uint4 each)
__device__ __forceinline__ const uint4* chunk_src(int q) {
    return (q < 16) ? (g_W1t + q * 512)
         : (q < 32) ? (g_W2t + (q - 16) * 512)
                    : (g_Memt + (q - 32) * 512);
}

// ================= main fused kernel =================
__global__ __launch_bounds__(NTHR, 3)
void ipm_mma(const float* __restrict__ X,
             const float* __restrict__ b1, const float* __restrict__ b2,
             const float* __restrict__ lng, const float* __restrict__ lnb,
             float* __restrict__ out, int ntok)
{
    extern __shared__ __align__(1024) char smem[];
    const uint32_t sb = smem_u32(smem);
    const int tid  = threadIdx.x;
    const int lane = tid & 31;
    const int w    = tid >> 5;
    const int mw   = w & 1;            // 2 M groups of 32 rows
    const int nw   = w >> 1;           // 4 N groups (n16 each per 64-chunk)
    const int tok0 = blockIdx.x * MTOK;

    float* sGg2 = reinterpret_cast<float*>(smem + GG2_BASE);
    float* sGb  = reinterpret_cast<float*>(smem + GB_BASE);
    float* sMu  = reinterpret_cast<float*>(smem + MU_OFF);
    float* sR   = reinterpret_cast<float*>(smem + R_OFF);
    float* sFsq = reinterpret_cast<float*>(smem + FSQ_OFF);
    float* sGm  = reinterpret_cast<float*>(smem + GM_OFF);
    float* sCM  = reinterpret_cast<float*>(smem + CM_OFF);

    const uint32_t lrow16 = lane & 15;
    const uint32_t asel   = lane >> 4;
    const uint32_t sxr    = lane & 7;
    const uint32_t bsel   = (lane >> 3) & 1;
    const uint32_t brow8  = (lane & 7) + ((lane >> 4) << 3);

    const uint32_t mb0 = sb + MBAR_BASE;
    const uint32_t mb1 = sb + MBAR_BASE + 8;

    // -------- prologue --------
    if (tid == 0) {
        MBARRIER_INIT(mb0, 1);
        MBARRIER_INIT(mb1, 1);
    }
    __syncthreads();
    if (tid == 0) {
        MBAR_EXPECT(mb0, 8192);
        BULK_G2S(sb + WB_BASE,        (const void*)chunk_src(0), 8192, mb0);
        MBAR_EXPECT(mb1, 8192);
        BULK_G2S(sb + WB_BASE + 8192, (const void*)chunk_src(1), 8192, mb1);
    }
    {
        float gv = lng[tid], bv = lnb[tid];
        sGg2[tid] = gv * gv;
        sGb[tid]  = gv * bv;
    }
    // X -> fp8 swizzled (64 rows x 256B)
    for (int q = tid; q < MTOK * 64; q += NTHR) {
        int r = q >> 6, k = (q & 63) * 4;
        int rg = tok0 + r; if (rg >= ntok) rg = ntok - 1;
        float4 v = *reinterpret_cast<const float4*>(&X[(long)rg * 256 + k]);
        uint32_t lo = pk8(v.x, v.y), hi = pk8(v.z, v.w);
        uint32_t pkd = lo | (hi << 16);
        int c = k >> 4;
        int cp = (c & 8) | ((c & 7) ^ (r & 7));
        *reinterpret_cast<uint32_t*>(smem + XA_BASE + r * 256 + (cp << 4) + (k & 15)) = pkd;
    }
    __syncthreads();

    // A-row bases (2 m16 tiles per warp)
    uint32_t aX[2], aH[2];
    #pragma unroll
    for (int t = 0; t < 2; t++) {
        aX[t] = sb + XA_BASE + (mw * 32 + 16 * t + lrow16) * 256;
        aH[t] = sb + H_BASE  + (mw * 32 + 16 * t + lrow16) * 512;
    }
    // B-row bases: warp's n16 in weight/Mem chunks (128B rows)
    uint32_t bW[2];
    #pragma unroll
    for (int b = 0; b < 2; b++)
        bW[b] = sb + WB_BASE + b * 8192 + (nw * 16 + brow8) * 128;

    // ================= GEMM1: H = relu(X @ W1 + b1) =================
    {
        float acc[2][2][4];
        for (int nb = 0; nb < 8; nb++) {
            #pragma unroll
            for (int t = 0; t < 2; t++)
                #pragma unroll
                for (int j = 0; j < 2; j++)
                    acc[t][j][0] = acc[t][j][1] = acc[t][j][2] = acc[t][j][3] = 0.f;

            for (int kc = 0; kc < 2; kc++) {
                const int q = nb * 2 + kc;
                const int buf = q & 1;
                MBAR_WAIT(buf ? mb1 : mb0, (q >> 1) & 1);
                #pragma unroll
                for (int kk = 0; kk < 4; kk++) {
                    uint32_t a[2][4], bfr[2][2];
                    uint32_t cA = (uint32_t)(2 * (kc * 4 + kk)) + asel;
                    uint32_t ksw = (((cA & 8) | ((cA & 7) ^ sxr)) << 4);
                    uint32_t ksb = (((uint32_t)(2 * kk) + bsel) ^ sxr) << 4;
                    #pragma unroll
                    for (int t = 0; t < 2; t++) LDSM4(a[t][0], a[t][1], a[t][2], a[t][3], aX[t] + ksw);
                    {
                        uint32_t r0, r1, r2, r3;
                        LDSM4(r0, r1, r2, r3, bW[buf] + ksb);
                        bfr[0][0] = r0; bfr[0][1] = r1;
                        bfr[1][0] = r2; bfr[1][1] = r3;
                    }
                    #pragma unroll
                    for (int t = 0; t < 2; t++)
                        #pragma unroll
                        for (int j = 0; j < 2; j++) mma8(acc[t][j], a[t], bfr[j]);
                }

                if (kc == 1) {   // epilogue: +b1, relu, fp8 u16 stores -> H
                    const int n0 = nb * 64 + nw * 16;
                    const uint32_t chunk = (uint32_t)(nb * 4 + nw);   // 0..31
                    #pragma unroll
                    for (int t = 0; t < 2; t++)
                        #pragma unroll
                        for (int gi = 0; gi < 2; gi++) {
                            float2 bc = __ldg((const float2*)&b1[n0 + 8 * gi + 2 * (lane & 3)]);
                            #pragma unroll
                            for (int rh = 0; rh < 2; rh++) {
                                int r = mw * 32 + 16 * t + 8 * rh + (lane >> 2);
                                float v0 = fmaxf(acc[t][gi][2 * rh]     + bc.x, 0.f);
                                float v1 = fmaxf(acc[t][gi][2 * rh + 1] + bc.y, 0.f);
                                uint32_t cp = (chunk & 24) | ((chunk & 7) ^ (uint32_t)(r & 7));
                                uint32_t off = (uint32_t)H_BASE + r * 512 + (cp << 4) + 8 * gi + 2 * (lane & 3);
                                *reinterpret_cast<uint16_t*>(smem + off) = (uint16_t)pk8(v0, v1);
                            }
                        }
                }
                __syncthreads();
                if (q + 2 < 34 && tid == 0) {
                    uint32_t m = buf ? mb1 : mb0;
                    MBAR_EXPECT(m, 8192);
                    BULK_G2S(sb + WB_BASE + buf * 8192, (const void*)chunk_src(q + 2), 8192, m);
                }
            }
        }
    }

    // ================= GEMM2: rawF = H @ W2 + b2 (5-sum stats on the fly) =================
    float st[2][2][5];
    #pragma unroll
    for (int t = 0; t < 2; t++)
        #pragma unroll
        for (int h = 0; h < 2; h++)
            #pragma unroll
            for (int i = 0; i < 5; i++) st[t][h][i] = 0.f;

    {
        float acc[2][2][4];
        for (int nc = 0; nc < 4; nc++) {
            #pragma unroll
            for (int t = 0; t < 2; t++)
                #pragma unroll
                for (int j = 0; j < 2; j++)
                    acc[t][j][0] = acc[t][j][1] = acc[t][j][2] = acc[t][j][3] = 0.f;

            for (int kc = 0; kc < 4; kc++) {
                const int q = 16 + nc * 4 + kc;
                const int buf = q & 1;
                MBAR_WAIT(buf ? mb1 : mb0, (q >> 1) & 1);
                #pragma unroll
                for (int kk = 0; kk < 4; kk++) {
                    uint32_t a[2][4], bfr[2][2];
                    uint32_t cA = (uint32_t)(2 * (kc * 4 + kk)) + asel;
                    uint32_t ksw = (((cA & 24) | ((cA & 7) ^ sxr)) << 4);
                    uint32_t ksb = (((uint32_t)(2 * kk) + bsel) ^ sxr) << 4;
                    #pragma unroll
                    for (int t = 0; t < 2; t++) LDSM4(a[t][0], a[t][1], a[t][2], a[t][3], aH[t] + ksw);
                    {
                        uint32_t r0, r1, r2, r3;
                        LDSM4(r0, r1, r2, r3, bW[buf] + ksb);
                        bfr[0][0] = r0; bfr[0][1] = r1;
                        bfr[1][0] = r2; bfr[1][1] = r3;
                    }
                    #pragma unroll
                    for (int t = 0; t < 2; t++)
                        #pragma unroll
                        for (int j = 0; j < 2; j++) mma8(acc[t][j], a[t], bfr[j]);
                }

                if (kc == 3) {   // epilogue: +b2, stats, fp8 rawF -> XA
                    const int n0 = nc * 64 + nw * 16;
                    const uint32_t chunk = (uint32_t)(nc * 4 + nw);   // 0..15
                    #pragma unroll
                    for (int t = 0; t < 2; t++)
                        #pragma unroll
                        for (int gi = 0; gi < 2; gi++) {
                            const int c00 = n0 + 8 * gi + 2 * (lane & 3);
                            float2 bc = __ldg((const float2*)&b2[c00]);
                            float2 G  = *reinterpret_cast<float2*>(sGg2 + c00);
                            float2 E  = *reinterpret_cast<float2*>(sGb + c00);
                            #pragma unroll
                            for (int rh = 0; rh < 2; rh++) {
                                int r = mw * 32 + 16 * t + 8 * rh + (lane >> 2);
                                float v0 = acc[t][gi][2 * rh]     + bc.x;
                                float v1 = acc[t][gi][2 * rh + 1] + bc.y;
                                st[t][rh][0] += v0 + v1;
                                st[t][rh][1] += v0 * v0 + v1 * v1;
                                st[t][rh][2] += G.x * v0 * v0 + G.y * v1 * v1;
                                st[t][rh][3] += G.x * v0 + G.y * v1;
                                st[t][rh][4] += E.x * v0 + E.y * v1;
                                uint32_t cp = (chunk & 8) | ((chunk & 7) ^ (uint32_t)(r & 7));
                                uint32_t off = (uint32_t)XA_BASE + r * 256 + (cp << 4) + 8 * gi + 2 * (lane & 3);
                                *reinterpret_cast<uint16_t*>(smem + off) = (uint16_t)pk8(v0, v1);
                            }
                        }
                }
                __syncthreads();
                if (q + 2 < 34 && tid == 0) {
                    uint32_t m = buf ? mb1 : mb0;
                    MBAR_EXPECT(m, 8192);
                    BULK_G2S(sb + WB_BASE + buf * 8192, (const void*)chunk_src(q + 2), 8192, m);
                }
            }
        }
    }

    // -------- stats: quad-reduce, partials to smem, combine --------
    {
        #pragma unroll
        for (int t = 0; t < 2; t++)
            #pragma unroll
            for (int h = 0; h < 2; h++)
                #pragma unroll
                for (int i = 0; i < 5; i++) {
                    float s = st[t][h][i];
                    s += __shfl_xor_sync(0xffffffffu, s, 1);
                    s += __shfl_xor_sync(0xffffffffu, s, 2);
                    st[t][h][i] = s;
                }
        if ((lane & 3) == 0) {
            #pragma unroll
            for (int t = 0; t < 2; t++)
                #pragma unroll
                for (int h = 0; h < 2; h++) {
                    int row = mw * 32 + 16 * t + 8 * h + (lane >> 2);
                    float* p = reinterpret_cast<float*>(smem + PART_OFF) + (row * 4 + nw) * 5;
                    #pragma unroll
                    for (int i = 0; i < 5; i++) p[i] = st[t][h][i];
                }
        }
        __syncthreads();

        if (tid < MTOK) {
            const float* p0 = reinterpret_cast<const float*>(smem + PART_OFF) + (tid * 4) * 5;
            float S1 = p0[0] + p0[5] + p0[10] + p0[15];
            float S2 = p0[1] + p0[6] + p0[11] + p0[16];
            float A2 = p0[2] + p0[7] + p0[12] + p0[17];
            float A1g = p0[3] + p0[8] + p0[13] + p0[18];
            float C1 = p0[4] + p0[9] + p0[14] + p0[19];
            float Sbb = __ldg(&g_cons[0]), Sgb = __ldg(&g_cons[1]), Sgg = __ldg(&g_cons[2]);
            float mu = S1 * (1.f / 256.f);
            float var = S2 * (1.f / 256.f) - mu * mu;
            float r = rsqrtf(var + 1e-5f);
            float fsq = r * r * A2 + 2.f * r * C1 - 2.f * mu * r * r * A1g
                      + Sbb - 2.f * mu * r * Sgb + mu * mu * r * r * Sgg;
            sMu[tid] = mu; sR[tid] = r; sFsq[tid] = fsq;
        }
        if (tid < 64) { sGm[tid] = __ldg(&g_gm[tid]); sCM[tid] = __ldg(&g_cM[tid]); }
        __syncthreads();
    }

    // ================= GEMM3: D = rawF @ (gamma.Mem)^T =================
    {
        MBAR_WAIT(mb0, 0);   // Mem chunk q=32
        MBAR_WAIT(mb1, 0);   // Mem chunk q=33

        float acc[2][2][4];
        #pragma unroll
        for (int t = 0; t < 2; t++)
            #pragma unroll
            for (int j = 0; j < 2; j++)
                acc[t][j][0] = acc[t][j][1] = acc[t][j][2] = acc[t][j][3] = 0.f;

        #pragma unroll
        for (int kk = 0; kk < 8; kk++) {
            const int buf = kk >> 2;
            uint32_t a[2][4], bfr[2][2];
            uint32_t cA = (uint32_t)(2 * kk) + asel;
            uint32_t ksw = (((cA & 8) | ((cA & 7) ^ sxr)) << 4);
            uint32_t c = (uint32_t)(2 * (kk & 3)) + bsel;
            uint32_t ksb = (c ^ sxr) << 4;
            #pragma unroll
            for (int t = 0; t < 2; t++) LDSM4(a[t][0], a[t][1], a[t][2], a[t][3], aX[t] + ksw);
            {
                uint32_t r0, r1, r2, r3;
                LDSM4(r0, r1, r2, r3, bW[buf] + ksb);
                bfr[0][0] = r0; bfr[0][1] = r1;
                bfr[1][0] = r2; bfr[1][1] = r3;
            }
            #pragma unroll
            for (int t = 0; t < 2; t++)
                #pragma unroll
                for (int j = 0; j < 2; j++) mma8(acc[t][j], a[t], bfr[j]);
        }

        // distances: d^2 = fsq + cM + 2*r*(mu*gm - D)
        #pragma unroll
        for (int t = 0; t < 2; t++) {
            int rA = mw * 32 + 16 * t + (lane >> 2), rB = rA + 8;
            float fA = sFsq[rA], rrA = sR[rA], muA = sMu[rA];
            float fB = sFsq[rB], rrB = sR[rB], muB = sMu[rB];
            #pragma unroll
            for (int j = 0; j < 2; j++) {
                int c0 = nw * 16 + 8 * j + 2 * (lane & 3);
                float gm0 = sGm[c0], gm1 = sGm[c0 + 1];
                float cm0 = sCM[c0], cm1 = sCM[c0 + 1];
                float2 dA, dB;
                dA.x = sqrtf(fmaxf(fA + cm0 + 2.f * rrA * (muA * gm0 - acc[t][j][0]), 0.f));
                dA.y = sqrtf(fmaxf(fA + cm1 + 2.f * rrA * (muA * gm1 - acc[t][j][1]), 0.f));
                dB.x = sqrtf(fmaxf(fB + cm0 + 2.f * rrB * (muB * gm0 - acc[t][j][2]), 0.f));
                dB.y = sqrtf(fmaxf(fB + cm1 + 2.f * rrB * (muB * gm1 - acc[t][j][3]), 0.f));
                *reinterpret_cast<float2*>(smem + H_BASE + rA * DIST_STRIDE + c0 * 4) = dA;
                *reinterpret_cast<float2*>(smem + H_BASE + rB * DIST_STRIDE + c0 * 4) = dB;
            }
        }
        __syncthreads();
    }

    // ================= top-5 + sigmoid =================
    if (tid < MTOK) {
        const float* dr = reinterpret_cast<const float*>(smem + H_BASE + tid * DIST_STRIDE);
        float b0 = FLT_MAX, bq1 = FLT_MAX, bq2 = FLT_MAX, bq3 = FLT_MAX, bq4 = FLT_MAX;
        #pragma unroll
        for (int m = 0; m < 50; m++) {
            float v = dr[m];
            if (v < bq4) {
                bq4 = v;
                if (bq4 < bq3) { float x = bq3; bq3 = bq4; bq4 = x; }
                if (bq3 < bq2) { float x = bq2; bq2 = bq3; bq3 = x; }
                if (bq2 < bq1) { float x = bq1; bq1 = bq2; bq2 = x; }
                if (bq1 < b0)  { float x = b0;  b0  = bq1; bq1 = x; }
            }
        }
        float avg = (b0 + bq1 + bq2 + bq3 + bq4) * 0.2f;
        int tg = tok0 + tid;
        if (tg < ntok) out[tg] = 1.f / (1.f + expf(1.f - avg));
    }
}

// ================= launch =================
extern "C" void kernel_launch(void* const* d_in, const int* in_sizes, int n_in,
                              void* d_out, int out_size) {
    const float* X   = (const float*)d_in[0];
    const float* Mem = (const float*)d_in[1];
    const float* W1  = (const float*)d_in[2];
    const float* b1  = (const float*)d_in[3];
    const float* W2  = (const float*)d_in[4];
    const float* b2  = (const float*)d_in[5];
    const float* g   = (const float*)d_in[6];
    const float* be  = (const float*)d_in[7];
    float* out = (float*)d_out;

    int ntok = out_size;
    int grid = (ntok + MTOK - 1) / MTOK;

    prep_weights2<<<1088, 256>>>(W1, W2, Mem, g);
    prep_red<<<65, 32>>>(Mem, g, be);

    cudaFuncSetAttribute(ipm_mma, cudaFuncAttributeMaxDynamicSharedMemorySize, SMEM_BYTES);
    ipm_mma<<<grid, NTHR, SMEM_BYTES>>>(X, b1, b2, g, be, out, ntok);
}

// round 13
// speedup vs baseline: 1.3059x; 1.0163x over previous
#include <cuda_runtime.h>
#include <cuda_bf16.h>
#include <math.h>
#include <float.h>
#include <stdint.h>

// ================= geometry =================
#define NTHR 288          // 8 compute warps + 1 producer warp
#define NCMP 256
#define MTOK 64

// smem byte map (fp8 images, MTOK=64, 8KB weight chunks)
#define XA_BASE   0          // X / raw-F fp8 image: 64 rows x 256B (16 KB)
#define H_BASE    16384      // H fp8 image: 64 rows x 512B (32 KB); later dists+stats
#define WB_BASE   49152      // 2 x 8 KB weight chunk buffers
#define GG2_BASE  65536      // 256 f32: gamma^2
#define GB_BASE   66560      // 256 f32: gamma*beta
#define MBAR_BASE 67584      // full0, full1, empty0, empty1 (4 x 8B)
#define SMEM_BYTES 67648

// inside H region, used AFTER GEMM2 is done (and after the post-GEMM2 CBAR)
#define PART_OFF  (H_BASE + 17408)   // [64][4][5] f32 partial sums
#define MU_OFF    (H_BASE + 22528)
#define R_OFF     (H_BASE + 22784)
#define FSQ_OFF   (H_BASE + 23040)
#define GM_OFF    (H_BASE + 23296)
#define CM_OFF    (H_BASE + 23552)

#define DIST_STRIDE 272

// device scratch: pre-swizzled fp8 weight images, 8KB chunks (n64 x k128, 128B rows)
__device__ uint4 g_W1t[8192];    // 16 chunks: q = (n>>6)*2 + (k>>7)
__device__ uint4 g_W2t[8192];    // 16 chunks: q = (n>>6)*4 + (k>>7)
__device__ uint4 g_Memt[1024];   // 2 chunks: q = k>>7 ; 64 rows, gamma-scaled
__device__ float g_gm[64];
__device__ float g_cM[64];
__device__ float g_cons[3];      // Sbb, Sgb, Sgg

// ================= asm helpers =================
__device__ __forceinline__ uint32_t smem_u32(const void* p) {
    uint32_t a;
    asm("{ .reg .u64 t; cvta.to.shared.u64 t, %1; cvt.u32.u64 %0, t; }" : "=r"(a) : "l"(p));
    return a;
}
#define LDSM4(r0, r1, r2, r3, a) \
    asm volatile("ldmatrix.sync.aligned.m8n8.x4.shared.b16 {%0,%1,%2,%3}, [%4];" \
        : "=r"(r0), "=r"(r1), "=r"(r2), "=r"(r3) : "r"(a))

#define MBARRIER_INIT(addr, cnt) \
    asm volatile("mbarrier.init.shared.b64 [%0], %1;" :: "r"((uint32_t)(addr)), "r"((uint32_t)(cnt)) : "memory")
#define MBAR_EXPECT(addr, bytes) \
    asm volatile("mbarrier.arrive.expect_tx.shared.b64 _, [%0], %1;" \
        :: "r"((uint32_t)(addr)), "r"((uint32_t)(bytes)) : "memory")
#define MBAR_ARRIVE(addr) \
    asm volatile("mbarrier.arrive.shared.b64 _, [%0];" :: "r"((uint32_t)(addr)) : "memory")
#define BULK_G2S(dst, src, bytes, mbar) \
    asm volatile("cp.async.bulk.shared::cta.global.mbarrier::complete_tx::bytes [%0], [%1], %2, [%3];" \
        :: "r"((uint32_t)(dst)), "l"(src), "r"((uint32_t)(bytes)), "r"((uint32_t)(mbar)) : "memory")
#define CBAR() asm volatile("bar.sync 1, 256;" ::: "memory")   // compute warps only

#define MBAR_WAIT(addr, par) do { \
    uint32_t _m = (uint32_t)(addr), _p = (uint32_t)(par), _d; \
    asm volatile("{\n\t.reg .pred p;\n\t" \
        "mbarrier.try_wait.parity.acquire.cta.shared::cta.b64 p, [%1], %2;\n\t" \
        "selp.b32 %0, 1, 0, p;\n\t}" : "=r"(_d) : "r"(_m), "r"(_p) : "memory"); \
    if (!_d) { \
        asm volatile("{\n\t.reg .pred P1;\n\t" \
            "WL_%=:\n\t" \
            "mbarrier.try_wait.parity.acquire.cta.shared::cta.b64 P1, [%0], %1, 0x989680;\n\t" \
            "@P1 bra.uni WD_%=;\n\t" \
            "bra.uni WL_%=;\n\t" \
            "WD_%=:\n\t}" :: "r"(_m), "r"(_p) : "memory"); \
    } \
} while (0)

// fp8 mma: m16n8k32 e4m3 x e4m3 -> f32
__device__ __forceinline__ void mma8(float* d, const uint32_t* a, const uint32_t* b) {
    asm volatile(
        "mma.sync.aligned.m16n8k32.row.col.f32.e4m3.e4m3.f32 "
        "{%0,%1,%2,%3}, {%4,%5,%6,%7}, {%8,%9}, {%0,%1,%2,%3};"
        : "+f"(d[0]), "+f"(d[1]), "+f"(d[2]), "+f"(d[3])
        : "r"(a[0]), "r"(a[1]), "r"(a[2]), "r"(a[3]), "r"(b[0]), "r"(b[1]));
}
// pack 2 floats -> 2 e4m3 (low byte = a)
__device__ __forceinline__ uint32_t pk8(float a, float b) {
    uint16_t r;
    asm("cvt.rn.satfinite.e4m3x2.f32 %0, %1, %2;" : "=h"(r) : "f"(b), "f"(a));
    return (uint32_t)r;
}

// ================= prep kernels =================
__global__ void prep_weights2(const float* __restrict__ W1, const float* __restrict__ W2,
                              const float* __restrict__ Mem, const float* __restrict__ lng) {
    int e = blockIdx.x * 256 + threadIdx.x;
    if (e < 131072) {                               // W1: [k=256][n=512]
        int n = e >> 8, k = e & 255;
        int q = (n >> 6) * 2 + (k >> 7);
        int np = n & 63, kl = k & 127;
        int c = kl >> 4;
        uint32_t off = (uint32_t)q * 8192u + np * 128u
                     + (uint32_t)(((c ^ (np & 7)) << 4) | (kl & 15));
        uint32_t p = pk8(W1[k * 512 + n], 0.f);
        *((uint8_t*)g_W1t + off) = (uint8_t)(p & 0xFF);
    } else if (e < 262144) {                        // W2: [k=512][n=256]
        int x = e - 131072;
        int n = x >> 9, k = x & 511;
        int q = (n >> 6) * 4 + (k >> 7);
        int np = n & 63, kl = k & 127;
        int c = kl >> 4;
        uint32_t off = (uint32_t)q * 8192u + np * 128u
                     + (uint32_t)(((c ^ (np & 7)) << 4) | (kl & 15));
        uint32_t p = pk8(W2[k * 256 + n], 0.f);
        *((uint8_t*)g_W2t + off) = (uint8_t)(p & 0xFF);
    } else if (e < 278528) {                        // Memt: 64 rows x k256, gamma-scaled
        int x = e - 262144;
        int m = x >> 8, k = x & 255;
        float v = (m < 50) ? Mem[m * 256 + k] * lng[k] : 0.f;
        int q = k >> 7, kl = k & 127;
        int c = kl >> 4;
        uint32_t off = (uint32_t)q * 8192u + m * 128u
                     + (uint32_t)(((c ^ (m & 7)) << 4) | (kl & 15));
        uint32_t p = pk8(v, 0.f);
        *((uint8_t*)g_Memt + off) = (uint8_t)(p & 0xFF);
    }
}

__global__ void prep_red(const float* __restrict__ Mem, const float* __restrict__ lng,
                         const float* __restrict__ lnb) {   // <<<65, 32>>>
    int b = blockIdx.x, lane = threadIdx.x;
    if (b < 64) {
        float msq = 0.f, gm = 0.f, bm = 0.f;
        if (b < 50) {
            #pragma unroll
            for (int j = 0; j < 8; j++) {
                int c = lane + 32 * j;
                float mv = Mem[b * 256 + c];
                msq += mv * mv; gm += lng[c] * mv; bm += lnb[c] * mv;
            }
        }
        #pragma unroll
        for (int o = 16; o; o >>= 1) {
            msq += __shfl_xor_sync(0xffffffffu, msq, o);
            gm  += __shfl_xor_sync(0xffffffffu, gm,  o);
            bm  += __shfl_xor_sync(0xffffffffu, bm,  o);
        }
        if (lane == 0) { g_gm[b] = gm; g_cM[b] = msq - 2.f * bm; }
    } else {
        float sbb = 0.f, sgb = 0.f, sgg = 0.f;
        #pragma unroll
        for (int j = 0; j < 8; j++) {
            int c = lane + 32 * j;
            float gv = lng[c], bv = lnb[c];
            sgg += gv * gv; sgb += gv * bv; sbb += bv * bv;
        }
        #pragma unroll
        for (int o = 16; o; o >>= 1) {
            sbb += __shfl_xor_sync(0xffffffffu, sbb, o);
            sgb += __shfl_xor_sync(0xffffffffu, sgb, o);
            sgg += __shfl_xor_sync(0xffffffffu, sgg, o);
        }
        if (lane == 0) { g_cons[0] = sbb; g_cons[1] = sgb; g_cons[2] = sgg; }
    }
}

// chunk source: 0..15 W1, 16..31 W2, 32..33 Mem  (512 uint4 each)
__device__ __forceinline__ const uint4* chunk_src(int q) {
    return (q < 16) ? (g_W1t + q * 512)
         : (q < 32) ? (g_W2t + (q - 16) * 512)
                    : (g_Memt + (q - 32) * 512);
}

// ================= main fused kernel =================
__global__ __launch_bounds__(NTHR, 3)
void ipm_mma(const float* __restrict__ X,
             const float* __restrict__ b1, const float* __restrict__ b2,
             const float* __restrict__ lng, const float* __restrict__ lnb,
             float* __restrict__ out, int ntok)
{
    extern __shared__ __align__(1024) char smem[];
    const uint32_t sb = smem_u32(smem);
    const int tid  = threadIdx.x;
    const int lane = tid & 31;
    const int w    = tid >> 5;
    const int mw   = w & 1;            // 2 M groups of 32 rows (compute warps)
    const int nw   = w >> 1;           // 4 N groups
    const int tok0 = blockIdx.x * MTOK;

    float* sGg2 = reinterpret_cast<float*>(smem + GG2_BASE);
    float* sGb  = reinterpret_cast<float*>(smem + GB_BASE);
    float* sMu  = reinterpret_cast<float*>(smem + MU_OFF);
    float* sR   = reinterpret_cast<float*>(smem + R_OFF);
    float* sFsq = reinterpret_cast<float*>(smem + FSQ_OFF);
    float* sGm  = reinterpret_cast<float*>(smem + GM_OFF);
    float* sCM  = reinterpret_cast<float*>(smem + CM_OFF);

    const uint32_t lrow16 = lane & 15;
    const uint32_t asel   = lane >> 4;
    const uint32_t sxr    = lane & 7;
    const uint32_t bsel   = (lane >> 3) & 1;
    const uint32_t brow8  = (lane & 7) + ((lane >> 4) << 3);

    const uint32_t fullB[2]  = { sb + MBAR_BASE,      sb + MBAR_BASE + 8  };
    const uint32_t emptyB[2] = { sb + MBAR_BASE + 16, sb + MBAR_BASE + 24 };

    // -------- prologue (all 288 threads) --------
    if (tid == 0) {
        MBARRIER_INIT(fullB[0], 1);
        MBARRIER_INIT(fullB[1], 1);
        MBARRIER_INIT(emptyB[0], 8);
        MBARRIER_INIT(emptyB[1], 8);
    }
    __syncthreads();

    if (w == 8) {
        // ================= producer warp =================
        if (lane == 0) {
            for (int q = 0; q < 34; q++) {
                const int stage = q & 1;
                const int pe = ((q >> 1) & 1) ^ 1;   // empty-phase, starts flipped
                MBAR_WAIT(emptyB[stage], pe);
                MBAR_EXPECT(fullB[stage], 8192);
                BULK_G2S(sb + WB_BASE + stage * 8192, (const void*)chunk_src(q), 8192, fullB[stage]);
            }
        }
        return;   // producer done; compute warps use bar.sync 1,256 from here on
    }

    // ================= compute warps (tid < 256) =================
    {
        float gv = lng[tid], bv = lnb[tid];
        sGg2[tid] = gv * gv;
        sGb[tid]  = gv * bv;
    }
    // X -> fp8 swizzled (64 rows x 256B)
    for (int q = tid; q < MTOK * 64; q += NCMP) {
        int r = q >> 6, k = (q & 63) * 4;
        int rg = tok0 + r; if (rg >= ntok) rg = ntok - 1;
        float4 v = *reinterpret_cast<const float4*>(&X[(long)rg * 256 + k]);
        uint32_t lo = pk8(v.x, v.y), hi = pk8(v.z, v.w);
        uint32_t pkd = lo | (hi << 16);
        int c = k >> 4;
        int cp = (c & 8) | ((c & 7) ^ (r & 7));
        *reinterpret_cast<uint32_t*>(smem + XA_BASE + r * 256 + (cp << 4) + (k & 15)) = pkd;
    }
    CBAR();

    // A-row bases (2 m16 tiles per warp)
    uint32_t aX[2], aH[2];
    #pragma unroll
    for (int t = 0; t < 2; t++) {
        aX[t] = sb + XA_BASE + (mw * 32 + 16 * t + lrow16) * 256;
        aH[t] = sb + H_BASE  + (mw * 32 + 16 * t + lrow16) * 512;
    }
    // B-row bases: warp's n16 in weight/Mem chunks (128B rows)
    uint32_t bW[2];
    #pragma unroll
    for (int b = 0; b < 2; b++)
        bW[b] = sb + WB_BASE + b * 8192 + (nw * 16 + brow8) * 128;

    // ================= GEMM1: H = relu(X @ W1 + b1) =================
    {
        float acc[2][2][4];
        for (int nb = 0; nb < 8; nb++) {
            #pragma unroll
            for (int t = 0; t < 2; t++)
                #pragma unroll
                for (int j = 0; j < 2; j++)
                    acc[t][j][0] = acc[t][j][1] = acc[t][j][2] = acc[t][j][3] = 0.f;

            for (int kc = 0; kc < 2; kc++) {
                const int q = nb * 2 + kc;
                const int stage = q & 1;
                MBAR_WAIT(fullB[stage], (q >> 1) & 1);
                #pragma unroll
                for (int kk = 0; kk < 4; kk++) {
                    uint32_t a[2][4], bfr[2][2];
                    uint32_t cA = (uint32_t)(2 * (kc * 4 + kk)) + asel;
                    uint32_t ksw = (((cA & 8) | ((cA & 7) ^ sxr)) << 4);
                    uint32_t ksb = (((uint32_t)(2 * kk) + bsel) ^ sxr) << 4;
                    #pragma unroll
                    for (int t = 0; t < 2; t++) LDSM4(a[t][0], a[t][1], a[t][2], a[t][3], aX[t] + ksw);
                    {
                        uint32_t r0, r1, r2, r3;
                        LDSM4(r0, r1, r2, r3, bW[stage] + ksb);
                        bfr[0][0] = r0; bfr[0][1] = r1;
                        bfr[1][0] = r2; bfr[1][1] = r3;
                    }
                    #pragma unroll
                    for (int t = 0; t < 2; t++)
                        #pragma unroll
                        for (int j = 0; j < 2; j++) mma8(acc[t][j], a[t], bfr[j]);
                }
                if (lane == 0) MBAR_ARRIVE(emptyB[stage]);

                if (kc == 1) {   // epilogue: +b1, relu, fp8 u16 stores -> H (own rows only)
                    const int n0 = nb * 64 + nw * 16;
                    const uint32_t chunk = (uint32_t)(nb * 4 + nw);
                    #pragma unroll
                    for (int t = 0; t < 2; t++)
                        #pragma unroll
                        for (int gi = 0; gi < 2; gi++) {
                            float2 bc = __ldg((const float2*)&b1[n0 + 8 * gi + 2 * (lane & 3)]);
                            #pragma unroll
                            for (int rh = 0; rh < 2; rh++) {
                                int r = mw * 32 + 16 * t + 8 * rh + (lane >> 2);
                                float v0 = fmaxf(acc[t][gi][2 * rh]     + bc.x, 0.f);
                                float v1 = fmaxf(acc[t][gi][2 * rh + 1] + bc.y, 0.f);
                                uint32_t cp = (chunk & 24) | ((chunk & 7) ^ (uint32_t)(r & 7));
                                uint32_t off = (uint32_t)H_BASE + r * 512 + (cp << 4) + 8 * gi + 2 * (lane & 3);
                                *reinterpret_cast<uint16_t*>(smem + off) = (uint16_t)pk8(v0, v1);
                            }
                        }
                }
            }
        }
    }
    CBAR();   // H complete across warps

    // ================= GEMM2: rawF = H @ W2 + b2 (5-sum stats on the fly) =================
    float st[2][2][5];
    #pragma unroll
    for (int t = 0; t < 2; t++)
        #pragma unroll
        for (int h = 0; h < 2; h++)
            #pragma unroll
            for (int i = 0; i < 5; i++) st[t][h][i] = 0.f;

    {
        float acc[2][2][4];
        for (int nc = 0; nc < 4; nc++) {
            #pragma unroll
            for (int t = 0; t < 2; t++)
                #pragma unroll
                for (int j = 0; j < 2; j++)
                    acc[t][j][0] = acc[t][j][1] = acc[t][j][2] = acc[t][j][3] = 0.f;

            for (int kc = 0; kc < 4; kc++) {
                const int q = 16 + nc * 4 + kc;
                const int stage = q & 1;
                MBAR_WAIT(fullB[stage], (q >> 1) & 1);
                #pragma unroll
                for (int kk = 0; kk < 4; kk++) {
                    uint32_t a[2][4], bfr[2][2];
                    uint32_t cA = (uint32_t)(2 * (kc * 4 + kk)) + asel;
                    uint32_t ksw = (((cA & 24) | ((cA & 7) ^ sxr)) << 4);
                    uint32_t ksb = (((uint32_t)(2 * kk) + bsel) ^ sxr) << 4;
                    #pragma unroll
                    for (int t = 0; t < 2; t++) LDSM4(a[t][0], a[t][1], a[t][2], a[t][3], aH[t] + ksw);
                    {
                        uint32_t r0, r1, r2, r3;
                        LDSM4(r0, r1, r2, r3, bW[stage] + ksb);
                        bfr[0][0] = r0; bfr[0][1] = r1;
                        bfr[1][0] = r2; bfr[1][1] = r3;
                    }
                    #pragma unroll
                    for (int t = 0; t < 2; t++)
                        #pragma unroll
                        for (int j = 0; j < 2; j++) mma8(acc[t][j], a[t], bfr[j]);
                }
                if (lane == 0) MBAR_ARRIVE(emptyB[stage]);

                if (kc == 3) {   // epilogue: +b2, stats, fp8 rawF -> XA (own rows only)
                    const int n0 = nc * 64 + nw * 16;
                    const uint32_t chunk = (uint32_t)(nc * 4 + nw);
                    #pragma unroll
                    for (int t = 0; t < 2; t++)
                        #pragma unroll
                        for (int gi = 0; gi < 2; gi++) {
                            const int c00 = n0 + 8 * gi + 2 * (lane & 3);
                            float2 bc = __ldg((const float2*)&b2[c00]);
                            float2 G  = *reinterpret_cast<float2*>(sGg2 + c00);
                            float2 E  = *reinterpret_cast<float2*>(sGb + c00);
                            #pragma unroll
                            for (int rh = 0; rh < 2; rh++) {
                                int r = mw * 32 + 16 * t + 8 * rh + (lane >> 2);
                                float v0 = acc[t][gi][2 * rh]     + bc.x;
                                float v1 = acc[t][gi][2 * rh + 1] + bc.y;
                                st[t][rh][0] += v0 + v1;
                                st[t][rh][1] += v0 * v0 + v1 * v1;
                                st[t][rh][2] += G.x * v0 * v0 + G.y * v1 * v1;
                                st[t][rh][3] += G.x * v0 + G.y * v1;
                                st[t][rh][4] += E.x * v0 + E.y * v1;
                                uint32_t cp = (chunk & 8) | ((chunk & 7) ^ (uint32_t)(r & 7));
                                uint32_t off = (uint32_t)XA_BASE + r * 256 + (cp << 4) + 8 * gi + 2 * (lane & 3);
                                *reinterpret_cast<uint16_t*>(smem + off) = (uint16_t)pk8(v0, v1);
                            }
                        }
                }
            }
        }
    }
    CBAR();   // *** RACE FIX: all warps done READING H before PART (aliases H rows 34+) is written ***

    // -------- stats: quad-reduce, partials to smem, combine --------
    {
        #pragma unroll
        for (int t = 0; t < 2; t++)
            #pragma unroll
            for (int h = 0; h < 2; h++)
                #pragma unroll
                for (int i = 0; i < 5; i++) {
                    float s = st[t][h][i];
                    s += __shfl_xor_sync(0xffffffffu, s, 1);
                    s += __shfl_xor_sync(0xffffffffu, s, 2);
                    st[t][h][i] = s;
                }
        if ((lane & 3) == 0) {
            #pragma unroll
            for (int t = 0; t < 2; t++)
                #pragma unroll
                for (int h = 0; h < 2; h++) {
                    int row = mw * 32 + 16 * t + 8 * h + (lane >> 2);
                    float* p = reinterpret_cast<float*>(smem + PART_OFF) + (row * 4 + nw) * 5;
                    #pragma unroll
                    for (int i = 0; i < 5; i++) p[i] = st[t][h][i];
                }
        }
        CBAR();

        if (tid < MTOK) {
            const float* p0 = reinterpret_cast<const float*>(smem + PART_OFF) + (tid * 4) * 5;
            float S1 = p0[0] + p0[5] + p0[10] + p0[15];
            float S2 = p0[1] + p0[6] + p0[11] + p0[16];
            float A2 = p0[2] + p0[7] + p0[12] + p0[17];
            float A1g = p0[3] + p0[8] + p0[13] + p0[18];
            float C1 = p0[4] + p0[9] + p0[14] + p0[19];
            float Sbb = __ldg(&g_cons[0]), Sgb = __ldg(&g_cons[1]), Sgg = __ldg(&g_cons[2]);
            float mu = S1 * (1.f / 256.f);
            float var = S2 * (1.f / 256.f) - mu * mu;
            float r = rsqrtf(var + 1e-5f);
            float fsq = r * r * A2 + 2.f * r * C1 - 2.f * mu * r * r * A1g
                      + Sbb - 2.f * mu * r * Sgb + mu * mu * r * r * Sgg;
            sMu[tid] = mu; sR[tid] = r; sFsq[tid] = fsq;
        }
        if (tid < 64) { sGm[tid] = __ldg(&g_gm[tid]); sCM[tid] = __ldg(&g_cM[tid]); }
        CBAR();
    }

    // ================= GEMM3: D = rawF @ (gamma.Mem)^T =================
    {
        MBAR_WAIT(fullB[0], 0);   // Mem chunk q=32 (17th completion of stage0 -> parity 0)
        MBAR_WAIT(fullB[1], 0);   // Mem chunk q=33

        float acc[2][2][4];
        #pragma unroll
        for (int t = 0; t < 2; t++)
            #pragma unroll
            for (int j = 0; j < 2; j++)
                acc[t][j][0] = acc[t][j][1] = acc[t][j][2] = acc[t][j][3] = 0.f;

        #pragma unroll
        for (int kk = 0; kk < 8; kk++) {
            const int stage = kk >> 2;
            uint32_t a[2][4], bfr[2][2];
            uint32_t cA = (uint32_t)(2 * kk) + asel;
            uint32_t ksw = (((cA & 8) | ((cA & 7) ^ sxr)) << 4);
            uint32_t c = (uint32_t)(2 * (kk & 3)) + bsel;
            uint32_t ksb = (c ^ sxr) << 4;
            #pragma unroll
            for (int t = 0; t < 2; t++) LDSM4(a[t][0], a[t][1], a[t][2], a[t][3], aX[t] + ksw);
            {
                uint32_t r0, r1, r2, r3;
                LDSM4(r0, r1, r2, r3, bW[stage] + ksb);
                bfr[0][0] = r0; bfr[0][1] = r1;
                bfr[1][0] = r2; bfr[1][1] = r3;
            }
            #pragma unroll
            for (int t = 0; t < 2; t++)
                #pragma unroll
                for (int j = 0; j < 2; j++) mma8(acc[t][j], a[t], bfr[j]);
        }

        // distances: d^2 = fsq + cM + 2*r*(mu*gm - D)
        #pragma unroll
        for (int t = 0; t < 2; t++) {
            int rA = mw * 32 + 16 * t + (lane >> 2), rB = rA + 8;
            float fA = sFsq[rA], rrA = sR[rA], muA = sMu[rA];
            float fB = sFsq[rB], rrB = sR[rB], muB = sMu[rB];
            #pragma unroll
            for (int j = 0; j < 2; j++) {
                int c0 = nw * 16 + 8 * j + 2 * (lane & 3);
                float gm0 = sGm[c0], gm1 = sGm[c0 + 1];
                float cm0 = sCM[c0], cm1 = sCM[c0 + 1];
                float2 dA, dB;
                dA.x = sqrtf(fmaxf(fA + cm0 + 2.f * rrA * (muA * gm0 - acc[t][j][0]), 0.f));
                dA.y = sqrtf(fmaxf(fA + cm1 + 2.f * rrA * (muA * gm1 - acc[t][j][1]), 0.f));
                dB.x = sqrtf(fmaxf(fB + cm0 + 2.f * rrB * (muB * gm0 - acc[t][j][2]), 0.f));
                dB.y = sqrtf(fmaxf(fB + cm1 + 2.f * rrB * (muB * gm1 - acc[t][j][3]), 0.f));
                *reinterpret_cast<float2*>(smem + H_BASE + rA * DIST_STRIDE + c0 * 4) = dA;
                *reinterpret_cast<float2*>(smem + H_BASE + rB * DIST_STRIDE + c0 * 4) = dB;
            }
        }
        CBAR();
    }

    // ================= top-5 + sigmoid =================
    if (tid < MTOK) {
        const float* dr = reinterpret_cast<const float*>(smem + H_BASE + tid * DIST_STRIDE);
        float b0 = FLT_MAX, bq1 = FLT_MAX, bq2 = FLT_MAX, bq3 = FLT_MAX, bq4 = FLT_MAX;
        #pragma unroll
        for (int m = 0; m < 50; m++) {
            float v = dr[m];
            if (v < bq4) {
                bq4 = v;
                if (bq4 < bq3) { float x = bq3; bq3 = bq4; bq4 = x; }
                if (bq3 < bq2) { float x = bq2; bq2 = bq3; bq3 = x; }
                if (bq2 < bq1) { float x = bq1; bq1 = bq2; bq2 = x; }
                if (bq1 < b0)  { float x = b0;  b0  = bq1; bq1 = x; }
            }
        }
        float avg = (b0 + bq1 + bq2 + bq3 + bq4) * 0.2f;
        int tg = tok0 + tid;
        if (tg < ntok) out[tg] = 1.f / (1.f + expf(1.f - avg));
    }
}

// ================= launch =================
extern "C" void kernel_launch(void* const* d_in, const int* in_sizes, int n_in,
                              void* d_out, int out_size) {
    const float* X   = (const float*)d_in[0];
    const float* Mem = (const float*)d_in[1];
    const float* W1  = (const float*)d_in[2];
    const float* b1  = (const float*)d_in[3];
    const float* W2  = (const float*)d_in[4];
    const float* b2  = (const float*)d_in[5];
    const float* g   = (const float*)d_in[6];
    const float* be  = (const float*)d_in[7];
    float* out = (float*)d_out;

    int ntok = out_size;
    int grid = (ntok + MTOK - 1) / MTOK;

    prep_weights2<<<1088, 256>>>(W1, W2, Mem, g);
    prep_red<<<65, 32>>>(Mem, g, be);

    cudaFuncSetAttribute(ipm_mma, cudaFuncAttributeMaxDynamicSharedMemorySize, SMEM_BYTES);
    ipm_mma<<<grid, NTHR, SMEM_BYTES>>>(X, b1, b2, g, be, out, ntok);
}